// round 1
// baseline (speedup 1.0000x reference)
#include <cuda_runtime.h>
#include <math.h>

#define DF 256      // feature dim
#define NE 8        // experts
#define TM 128      // rows per tile
#define TN 128      // output-cols per n-chunk
#define TK 16       // k-chunk
#define SHS 129     // sH row stride (pad: conflict-free GEMM2 A-reads)
#define MAXB 65536

// ---------------- routing scratch (device globals: no allocation) ----------
__device__ int g_counts[NE];
__device__ int g_cursor[NE];
__device__ int g_offsets[NE + 1];
__device__ int g_perm[MAXB];

__global__ void k_zero() {
    int i = threadIdx.x;
    if (i < NE) { g_counts[i] = 0; g_cursor[i] = 0; }
}

__device__ __forceinline__ int expert_of(float t) {
    int e = (int)(t * 8.0f);          // h = 1/8 exactly; matches t/h trunc
    if (e > NE - 1) e = NE - 1;
    if (e < 0) e = 0;
    return e;
}

__global__ void k_count(const float* __restrict__ t, int B) {
    int i = blockIdx.x * blockDim.x + threadIdx.x;
    if (i < B) atomicAdd(&g_counts[expert_of(t[i])], 1);
}

__global__ void k_scan() {
    int acc = 0;
    for (int e = 0; e < NE; e++) { g_offsets[e] = acc; acc += g_counts[e]; }
    g_offsets[NE] = acc;
}

__global__ void k_scatter(const float* __restrict__ t, int B) {
    int i = blockIdx.x * blockDim.x + threadIdx.x;
    if (i < B) {
        int e = expert_of(t[i]);
        int pos = g_offsets[e] + atomicAdd(&g_cursor[e], 1);
        g_perm[pos] = i;
    }
}

// ---------------- main fused MoE kernel ------------------------------------
__global__ __launch_bounds__(256, 1) void k_moe(
    const float* __restrict__ y,  const float* __restrict__ W1,
    const float* __restrict__ b1, const float* __restrict__ W2,
    const float* __restrict__ b2, const float* __restrict__ scales,
    const float* __restrict__ shifta, const float* __restrict__ shiftb,
    float* __restrict__ out)
{
    extern __shared__ float smem[];
    float* sA = smem;                 // [TK][TM]  = 2048 f
    float* sB = sA + TK * TM;         // [TK][TN]  = 2048 f
    float* sH = sB + TK * TN;         // [DF][SHS] = 33024 f  (H^T: [n][m])
    int*  sPerm = (int*)(sH + DF * SHS);  // [TM]

    // ---- map block -> (expert, local tile) --------------------------------
    int bid = blockIdx.x;
    int e = 0, local = -1, acc_t = 0;
    #pragma unroll
    for (int q = 0; q < NE; q++) {
        int cnt = g_offsets[q + 1] - g_offsets[q];
        int nt  = (cnt + TM - 1) / TM;
        if (local < 0 && bid < acc_t + nt) { e = q; local = bid - acc_t; }
        acc_t += nt;
    }
    if (local < 0) return;   // uniform per block

    int base = g_offsets[e] + local * TM;
    int rows = g_offsets[e + 1] - base;
    if (rows > TM) rows = TM;

    int tid = threadIdx.x;
    if (tid < TM) sPerm[tid] = (tid < rows) ? g_perm[base + tid] : g_perm[base];
    __syncthreads();

    int tx = tid & 15;   // 0..15  -> n
    int ty = tid >> 4;   // 0..15  -> m
    const float* W1e = W1 + (size_t)e * DF * DF;
    const float* W2e = W2 + (size_t)e * DF * DF;

    // =========== GEMM1: H[n][m] = tanh( sum_k Y[m][k] * W1e[n][k] + b1 ) ===
    for (int nh = 0; nh < 2; nh++) {
        int n0 = nh * TN;
        float acc[8][8];
        #pragma unroll
        for (int i = 0; i < 8; i++)
            #pragma unroll
            for (int j = 0; j < 8; j++) acc[i][j] = 0.0f;

        for (int kc = 0; kc < DF / TK; kc++) {
            int k0 = kc * TK;
            // gather A tile: 128 rows x 16 k (512 float4; 2 per thread)
            #pragma unroll
            for (int u = 0; u < 2; u++) {
                int v = tid * 2 + u;
                int r = v >> 2, kq = v & 3;
                const float4 d = *(const float4*)(y + (size_t)sPerm[r] * DF + k0 + kq * 4);
                sA[(kq * 4 + 0) * TM + r] = d.x;
                sA[(kq * 4 + 1) * TM + r] = d.y;
                sA[(kq * 4 + 2) * TM + r] = d.z;
                sA[(kq * 4 + 3) * TM + r] = d.w;
            }
            // B tile: W1e rows [n0, n0+128), k chunk
            #pragma unroll
            for (int u = 0; u < 2; u++) {
                int v = tid * 2 + u;
                int r = v >> 2, kq = v & 3;
                const float4 d = *(const float4*)(W1e + (size_t)(n0 + r) * DF + k0 + kq * 4);
                sB[(kq * 4 + 0) * TN + r] = d.x;
                sB[(kq * 4 + 1) * TN + r] = d.y;
                sB[(kq * 4 + 2) * TN + r] = d.z;
                sB[(kq * 4 + 3) * TN + r] = d.w;
            }
            __syncthreads();
            #pragma unroll
            for (int kk = 0; kk < TK; kk++) {
                float ra[8], rb[8];
                *(float4*)&ra[0] = *(float4*)&sA[kk * TM + ty * 8];
                *(float4*)&ra[4] = *(float4*)&sA[kk * TM + ty * 8 + 4];
                *(float4*)&rb[0] = *(float4*)&sB[kk * TN + tx * 8];
                *(float4*)&rb[4] = *(float4*)&sB[kk * TN + tx * 8 + 4];
                #pragma unroll
                for (int i = 0; i < 8; i++)
                    #pragma unroll
                    for (int j = 0; j < 8; j++)
                        acc[i][j] = fmaf(ra[i], rb[j], acc[i][j]);
            }
            __syncthreads();
        }
        // epilogue: tanh + bias -> sH (transposed [n][m], stride SHS)
        #pragma unroll
        for (int j = 0; j < 8; j++) {
            int n = n0 + tx * 8 + j;
            float bb = b1[e * DF + n];
            #pragma unroll
            for (int i = 0; i < 8; i++)
                sH[n * SHS + ty * 8 + i] = tanhf(acc[i][j] + bb);
        }
    }

    // epilogue constants
    float sa  = 1.0f / (1.0f + expf(-shifta[0]));
    float sb_ = 1.0f / (1.0f + expf(-shiftb[0]));
    float av = -sa;          // EIGINIT + sig*(EIGMIN-EIGINIT)
    float bv =  sb_;         // EIGINIT + sig*(EIGMAX-EIGINIT)
    float cf = 0.5f * (bv - av);
    float cy = 0.5f * (av + bv);

    // =========== GEMM2: OUT = H @ W2e^T + b2, fused epilogue ===============
    for (int nh = 0; nh < 2; nh++) {
        int n0 = nh * TN;
        float acc[8][8];
        #pragma unroll
        for (int i = 0; i < 8; i++)
            #pragma unroll
            for (int j = 0; j < 8; j++) acc[i][j] = 0.0f;

        for (int kc = 0; kc < DF / TK; kc++) {
            int k0 = kc * TK;
            // B tile from W2e
            #pragma unroll
            for (int u = 0; u < 2; u++) {
                int v = tid * 2 + u;
                int r = v >> 2, kq = v & 3;
                const float4 d = *(const float4*)(W2e + (size_t)(n0 + r) * DF + k0 + kq * 4);
                sB[(kq * 4 + 0) * TN + r] = d.x;
                sB[(kq * 4 + 1) * TN + r] = d.y;
                sB[(kq * 4 + 2) * TN + r] = d.z;
                sB[(kq * 4 + 3) * TN + r] = d.w;
            }
            __syncthreads();   // also orders sH writes (GEMM1) before reads
            #pragma unroll
            for (int kk = 0; kk < TK; kk++) {
                float ra[8], rb[8];
                #pragma unroll
                for (int i = 0; i < 8; i++)
                    ra[i] = sH[(k0 + kk) * SHS + ty * 8 + i];
                *(float4*)&rb[0] = *(float4*)&sB[kk * TN + tx * 8];
                *(float4*)&rb[4] = *(float4*)&sB[kk * TN + tx * 8 + 4];
                #pragma unroll
                for (int i = 0; i < 8; i++)
                    #pragma unroll
                    for (int j = 0; j < 8; j++)
                        acc[i][j] = fmaf(ra[i], rb[j], acc[i][j]);
            }
            __syncthreads();
        }
        // fused epilogue + scatter
        float c1[8], bb2[8];
        #pragma unroll
        for (int j = 0; j < 8; j++) {
            int n = n0 + tx * 8 + j;
            float sg = 1.0f / (1.0f + expf(-scales[n]));
            c1[j] = cf * sg;
            bb2[j] = b2[e * DF + n];
        }
        #pragma unroll
        for (int i = 0; i < 8; i++) {
            int m = ty * 8 + i;
            if (m < rows) {
                int row = sPerm[m];
                const float4 y0 = *(const float4*)(y + (size_t)row * DF + n0 + tx * 8);
                const float4 y1 = *(const float4*)(y + (size_t)row * DF + n0 + tx * 8 + 4);
                float4 o0, o1;
                o0.x = c1[0] * (acc[i][0] + bb2[0]) + cy * y0.x;
                o0.y = c1[1] * (acc[i][1] + bb2[1]) + cy * y0.y;
                o0.z = c1[2] * (acc[i][2] + bb2[2]) + cy * y0.z;
                o0.w = c1[3] * (acc[i][3] + bb2[3]) + cy * y0.w;
                o1.x = c1[4] * (acc[i][4] + bb2[4]) + cy * y1.x;
                o1.y = c1[5] * (acc[i][5] + bb2[5]) + cy * y1.y;
                o1.z = c1[6] * (acc[i][6] + bb2[6]) + cy * y1.z;
                o1.w = c1[7] * (acc[i][7] + bb2[7]) + cy * y1.w;
                *(float4*)(out + (size_t)row * DF + n0 + tx * 8)     = o0;
                *(float4*)(out + (size_t)row * DF + n0 + tx * 8 + 4) = o1;
            }
        }
    }
}

// ---------------- launcher ---------------------------------------------------
extern "C" void kernel_launch(void* const* d_in, const int* in_sizes, int n_in,
                              void* d_out, int out_size)
{
    const float* t      = (const float*)d_in[0];
    const float* y      = (const float*)d_in[1];
    const float* W1     = (const float*)d_in[2];
    const float* b1     = (const float*)d_in[3];
    const float* W2     = (const float*)d_in[4];
    const float* b2     = (const float*)d_in[5];
    const float* scales = (const float*)d_in[6];
    const float* sha    = (const float*)d_in[7];
    const float* shb    = (const float*)d_in[8];
    float* out = (float*)d_out;
    int B = in_sizes[0];

    k_zero<<<1, 32>>>();
    int thr = 256;
    k_count<<<(B + thr - 1) / thr, thr>>>(t, B);
    k_scan<<<1, 1>>>();
    k_scatter<<<(B + thr - 1) / thr, thr>>>(t, B);

    size_t smem = (size_t)(TK * TM + TK * TN + DF * SHS) * sizeof(float)
                + TM * sizeof(int);
    cudaFuncSetAttribute(k_moe, cudaFuncAttributeMaxDynamicSharedMemorySize, (int)smem);
    int grid = (B + TM - 1) / TM + NE;
    k_moe<<<grid, 256, smem>>>(y, W1, b1, W2, b2, scales, sha, shb, out);
}

// round 3
// speedup vs baseline: 2.4618x; 2.4618x over previous
#include <cuda_runtime.h>
#include <cuda_bf16.h>
#include <stdint.h>
#include <math.h>

#define DF 256
#define NE 8
#define TM 128
#define MAXB 65536

// ---- smem layout (bytes) ----
#define OFF_PERM 0
#define OFF_B1   512
#define OFF_B2   1536
#define OFF_C1   2560
#define OFF_AHI  3584
#define ASTRIDE  528                        // 264 bf16/row (pad: conflict-free LDSM)
#define OFF_ALO  (OFF_AHI + 128*ASTRIDE)    // 71168
#define OFF_BB   (OFF_ALO + 128*ASTRIDE)    // 138752
#define BSTRIDE  80                         // 40 bf16/row
#define BLO      20480                      // lo plane within a B buffer
#define BBUF     40960                      // hi+lo per buffer
#define SMEM_BYTES (OFF_BB + 2*BBUF)        // 220672

// ---------------- routing ----------------------------------------------------
__device__ int g_counts[NE];
__device__ int g_cursor[NE];
__device__ int g_offsets[NE + 1];
__device__ int g_perm[MAXB];

__device__ __forceinline__ int expert_of(float t) {
    int e = (int)(t * 8.0f);
    if (e > NE - 1) e = NE - 1;
    if (e < 0) e = 0;
    return e;
}

__global__ void k_zero() {
    int i = threadIdx.x;
    if (i < NE) { g_counts[i] = 0; g_cursor[i] = 0; }
}

__global__ void k_count(const float* __restrict__ t, int B) {
    __shared__ int h[NE];
    if (threadIdx.x < NE) h[threadIdx.x] = 0;
    __syncthreads();
    int i = blockIdx.x * blockDim.x + threadIdx.x;
    if (i < B) atomicAdd(&h[expert_of(t[i])], 1);
    __syncthreads();
    if (threadIdx.x < NE && h[threadIdx.x]) atomicAdd(&g_counts[threadIdx.x], h[threadIdx.x]);
}

__global__ void k_scan() {
    int acc = 0;
    for (int e = 0; e < NE; e++) { g_offsets[e] = acc; acc += g_counts[e]; }
    g_offsets[NE] = acc;
}

__global__ void k_scatter(const float* __restrict__ t, int B) {
    __shared__ int h[NE], bb[NE];
    if (threadIdx.x < NE) h[threadIdx.x] = 0;
    __syncthreads();
    int i = blockIdx.x * blockDim.x + threadIdx.x;
    int e = 0, r = 0;
    bool valid = (i < B);
    if (valid) { e = expert_of(t[i]); r = atomicAdd(&h[e], 1); }
    __syncthreads();
    if (threadIdx.x < NE && h[threadIdx.x]) bb[threadIdx.x] = atomicAdd(&g_cursor[threadIdx.x], h[threadIdx.x]);
    __syncthreads();
    if (valid) g_perm[g_offsets[e] + bb[e] + r] = i;
}

// ---------------- helpers -----------------------------------------------------
__device__ __forceinline__ void cvt2(float a, float b, uint32_t& hi, uint32_t& lo) {
    __nv_bfloat162 h = __floats2bfloat162_rn(a, b);
    float ra = a - __bfloat162float(h.x);
    float rb = b - __bfloat162float(h.y);
    __nv_bfloat162 l = __floats2bfloat162_rn(ra, rb);
    hi = *reinterpret_cast<uint32_t*>(&h);
    lo = *reinterpret_cast<uint32_t*>(&l);
}

__device__ __forceinline__ float sigmf(float x) { return 1.0f / (1.0f + expf(-x)); }

__device__ __forceinline__ void ldsm4(uint32_t* r, uint32_t addr) {
    asm volatile("ldmatrix.sync.aligned.m8n8.x4.shared.b16 {%0,%1,%2,%3}, [%4];"
        : "=r"(r[0]), "=r"(r[1]), "=r"(r[2]), "=r"(r[3]) : "r"(addr));
}
__device__ __forceinline__ void ldsm2(uint32_t* r, uint32_t addr) {
    asm volatile("ldmatrix.sync.aligned.m8n8.x2.shared.b16 {%0,%1}, [%2];"
        : "=r"(r[0]), "=r"(r[1]) : "r"(addr));
}
__device__ __forceinline__ void mma_bf16(float* d, const uint32_t* a, const uint32_t* b) {
    asm volatile("mma.sync.aligned.m16n8k16.row.col.f32.bf16.bf16.f32 "
        "{%0,%1,%2,%3}, {%4,%5,%6,%7}, {%8,%9}, {%0,%1,%2,%3};"
        : "+f"(d[0]), "+f"(d[1]), "+f"(d[2]), "+f"(d[3])
        : "r"(a[0]), "r"(a[1]), "r"(a[2]), "r"(a[3]), "r"(b[0]), "r"(b[1]));
}

// ---------------- GEMM: acc[2][16][4] += A(smem,split) x W^T (split, 3-term) --
__device__ __forceinline__ void gemm256(
    char* smem, uint32_t su, const float* __restrict__ W,
    float (&acc)[2][16][4], int lane, int wm, int wn, int tid)
{
    const int lr = lane & 7, grp = lane >> 3;
    const uint32_t aRowB = (uint32_t)(wm * 32 + (grp & 1) * 8 + lr) * ASTRIDE;
    const uint32_t aColE = (uint32_t)(grp >> 1) * 8;   // elems
    const uint32_t bOffB = (uint32_t)(lane & 7) * BSTRIDE + (uint32_t)((lane >> 3) & 1) * 16;

    // prologue: chunk 0 -> buf 0
    {
        float4 st[8];
#pragma unroll
        for (int u = 0; u < 8; u++) {
            int v = tid + 256 * u;
            int n = v >> 3, q = v & 7;
            st[u] = *(const float4*)(W + (size_t)n * DF + q * 4);
        }
        char* bh = smem + OFF_BB;
#pragma unroll
        for (int u = 0; u < 8; u++) {
            int v = tid + 256 * u;
            int n = v >> 3, q = v & 7;
            uint32_t h0, l0, h1, l1;
            cvt2(st[u].x, st[u].y, h0, l0);
            cvt2(st[u].z, st[u].w, h1, l1);
            uint32_t off = n * BSTRIDE + q * 8;
            *(uint32_t*)(bh + off)           = h0;
            *(uint32_t*)(bh + off + 4)       = h1;
            *(uint32_t*)(bh + BLO + off)     = l0;
            *(uint32_t*)(bh + BLO + off + 4) = l1;
        }
    }
    __syncthreads();

    for (int kc = 0; kc < 8; kc++) {
        int buf = kc & 1;
        bool has = (kc + 1 < 8);
        float4 st[8];
        if (has) {
#pragma unroll
            for (int u = 0; u < 8; u++) {
                int v = tid + 256 * u;
                int n = v >> 3, q = v & 7;
                st[u] = *(const float4*)(W + (size_t)n * DF + (kc + 1) * 32 + q * 4);
            }
        }

#pragma unroll
        for (int ks = 0; ks < 2; ks++) {
            uint32_t k0 = (uint32_t)(kc * 32 + ks * 16);
            uint32_t abase = aRowB + (k0 + aColE) * 2;
            uint32_t ah0[4], ah1[4], al0[4], al1[4];
            ldsm4(ah0, su + OFF_AHI + abase);
            ldsm4(ah1, su + OFF_AHI + abase + 16 * ASTRIDE);
            ldsm4(al0, su + OFF_ALO + abase);
            ldsm4(al1, su + OFF_ALO + abase + 16 * ASTRIDE);
            uint32_t bbase = su + OFF_BB + buf * BBUF + bOffB + ks * 32;
#pragma unroll
            for (int nt = 0; nt < 16; nt++) {
                int n = (nt < 8) ? (wn * 64 + nt * 8) : (128 + wn * 64 + (nt - 8) * 8);
                uint32_t bh[2], bl[2];
                ldsm2(bh, bbase + n * BSTRIDE);
                ldsm2(bl, bbase + n * BSTRIDE + BLO);
                mma_bf16(acc[0][nt], ah0, bh);
                mma_bf16(acc[1][nt], ah1, bh);
                mma_bf16(acc[0][nt], ah0, bl);
                mma_bf16(acc[1][nt], ah1, bl);
                mma_bf16(acc[0][nt], al0, bh);
                mma_bf16(acc[1][nt], al1, bh);
            }
        }

        if (has) {
            char* bh = smem + OFF_BB + ((kc + 1) & 1) * BBUF;
#pragma unroll
            for (int u = 0; u < 8; u++) {
                int v = tid + 256 * u;
                int n = v >> 3, q = v & 7;
                uint32_t h0, l0, h1, l1;
                cvt2(st[u].x, st[u].y, h0, l0);
                cvt2(st[u].z, st[u].w, h1, l1);
                uint32_t off = n * BSTRIDE + q * 8;
                *(uint32_t*)(bh + off)           = h0;
                *(uint32_t*)(bh + off + 4)       = h1;
                *(uint32_t*)(bh + BLO + off)     = l0;
                *(uint32_t*)(bh + BLO + off + 4) = l1;
            }
            __syncthreads();
        }
    }
}

// ---------------- main fused MoE kernel (mma.sync split-bf16) -----------------
__global__ __launch_bounds__(256, 1) void k_moe(
    const float* __restrict__ y,  const float* __restrict__ W1,
    const float* __restrict__ b1, const float* __restrict__ W2,
    const float* __restrict__ b2, const float* __restrict__ scales,
    const float* __restrict__ shifta, const float* __restrict__ shiftb,
    float* __restrict__ out)
{
    extern __shared__ char smem[];
    const int tid  = threadIdx.x;
    const int lane = tid & 31;
    const int wid  = tid >> 5;
    const int wm   = wid & 3;     // 4 warps along M
    const int wn   = wid >> 2;    // 2 warps along N

    // ---- block -> (expert, tile) -------------------------------------------
    int bid = blockIdx.x, e = 0, local = -1, acc_t = 0;
#pragma unroll
    for (int q = 0; q < NE; q++) {
        int cnt = g_offsets[q + 1] - g_offsets[q];
        int nt  = (cnt + TM - 1) / TM;
        if (local < 0 && bid < acc_t + nt) { e = q; local = bid - acc_t; }
        acc_t += nt;
    }
    if (local < 0) return;
    int base = g_offsets[e] + local * TM;
    int rows = g_offsets[e + 1] - base;
    if (rows > TM) rows = TM;

    uint32_t su;
    asm("{ .reg .u64 t; cvta.to.shared.u64 t, %1; cvt.u32.u64 %0, t; }" : "=r"(su) : "l"(smem));

    int*   sPerm = (int*)(smem + OFF_PERM);
    float* sB1   = (float*)(smem + OFF_B1);
    float* sB2   = (float*)(smem + OFF_B2);
    float* sC1   = (float*)(smem + OFF_C1);

    if (tid < TM) sPerm[tid] = (tid < rows) ? g_perm[base + tid] : g_perm[base];
    float sa = sigmf(shifta[0]);
    float sb = sigmf(shiftb[0]);
    float cy = 0.5f * (sb - sa);
    sB1[tid] = b1[e * DF + tid];
    sB2[tid] = b2[e * DF + tid];
    sC1[tid] = 0.5f * (sb + sa) * sigmf(scales[tid]);
    __syncthreads();

    const float* W1e = W1 + (size_t)e * DF * DF;
    const float* W2e = W2 + (size_t)e * DF * DF;

    // ---- gather Y rows -> A hi/lo ------------------------------------------
#pragma unroll 4
    for (int u = 0; u < 32; u++) {
        int v = tid + 256 * u;
        int r = v >> 6, q = v & 63;
        float4 d = *(const float4*)(y + (size_t)sPerm[r] * DF + q * 4);
        uint32_t h0, l0, h1, l1;
        cvt2(d.x, d.y, h0, l0);
        cvt2(d.z, d.w, h1, l1);
        uint32_t off = (uint32_t)r * ASTRIDE + q * 8;
        *(uint32_t*)(smem + OFF_AHI + off)     = h0;
        *(uint32_t*)(smem + OFF_AHI + off + 4) = h1;
        *(uint32_t*)(smem + OFF_ALO + off)     = l0;
        *(uint32_t*)(smem + OFF_ALO + off + 4) = l1;
    }

    float acc[2][16][4];
#pragma unroll
    for (int i = 0; i < 2; i++)
#pragma unroll
        for (int j = 0; j < 16; j++)
#pragma unroll
            for (int c = 0; c < 4; c++) acc[i][j][c] = 0.0f;

    // =================== GEMM1 ===============================================
    gemm256(smem, su, W1e, acc, lane, wm, wn, tid);

    // ---- H = tanh(acc + b1) -> overwrite A (own rows only) ------------------
#pragma unroll
    for (int mt = 0; mt < 2; mt++)
#pragma unroll
        for (int sub = 0; sub < 2; sub++) {
            int m = wm * 32 + mt * 16 + sub * 8 + (lane >> 2);
#pragma unroll
            for (int nt = 0; nt < 16; nt++) {
                int n = ((nt < 8) ? (wn * 64 + nt * 8) : (128 + wn * 64 + (nt - 8) * 8)) + (lane & 3) * 2;
                float h0 = tanhf(acc[mt][nt][sub * 2 + 0] + sB1[n]);
                float h1 = tanhf(acc[mt][nt][sub * 2 + 1] + sB1[n + 1]);
                uint32_t hh, ll;
                cvt2(h0, h1, hh, ll);
                uint32_t off = (uint32_t)m * ASTRIDE + n * 2;
                *(uint32_t*)(smem + OFF_AHI + off) = hh;
                *(uint32_t*)(smem + OFF_ALO + off) = ll;
            }
        }

#pragma unroll
    for (int i = 0; i < 2; i++)
#pragma unroll
        for (int j = 0; j < 16; j++)
#pragma unroll
            for (int c = 0; c < 4; c++) acc[i][j][c] = 0.0f;

    // =================== GEMM2 ===============================================
    gemm256(smem, su, W2e, acc, lane, wm, wn, tid);

    // ---- epilogue: out = c1*(acc + b2) + cy*y, scattered --------------------
#pragma unroll
    for (int mt = 0; mt < 2; mt++)
#pragma unroll
        for (int sub = 0; sub < 2; sub++) {
            int m = wm * 32 + mt * 16 + sub * 8 + (lane >> 2);
            if (m < rows) {
                int row = sPerm[m];
#pragma unroll
                for (int nt = 0; nt < 16; nt++) {
                    int n = ((nt < 8) ? (wn * 64 + nt * 8) : (128 + wn * 64 + (nt - 8) * 8)) + (lane & 3) * 2;
                    float2 yv = *(const float2*)(y + (size_t)row * DF + n);
                    float2 o;
                    o.x = sC1[n]     * (acc[mt][nt][sub * 2 + 0] + sB2[n])     + cy * yv.x;
                    o.y = sC1[n + 1] * (acc[mt][nt][sub * 2 + 1] + sB2[n + 1]) + cy * yv.y;
                    *(float2*)(out + (size_t)row * DF + n) = o;
                }
            }
        }
}

// ---------------- launcher ---------------------------------------------------
extern "C" void kernel_launch(void* const* d_in, const int* in_sizes, int n_in,
                              void* d_out, int out_size)
{
    const float* t      = (const float*)d_in[0];
    const float* y      = (const float*)d_in[1];
    const float* W1     = (const float*)d_in[2];
    const float* b1     = (const float*)d_in[3];
    const float* W2     = (const float*)d_in[4];
    const float* b2     = (const float*)d_in[5];
    const float* scales = (const float*)d_in[6];
    const float* sha    = (const float*)d_in[7];
    const float* shb    = (const float*)d_in[8];
    float* out = (float*)d_out;
    int B = in_sizes[0];

    k_zero<<<1, 32>>>();
    int nb = (B + 255) / 256;
    k_count<<<nb, 256>>>(t, B);
    k_scan<<<1, 1>>>();
    k_scatter<<<nb, 256>>>(t, B);

    cudaFuncSetAttribute(k_moe, cudaFuncAttributeMaxDynamicSharedMemorySize, SMEM_BYTES);
    int grid = (B + TM - 1) / TM + NE;
    k_moe<<<grid, 256, SMEM_BYTES>>>(y, W1, b1, W2, b2, scales, sha, shb, out);
}

// round 4
// speedup vs baseline: 3.1530x; 1.2808x over previous
#include <cuda_runtime.h>
#include <cuda_fp16.h>
#include <stdint.h>
#include <math.h>

#define DF 256
#define NE 8
#define TM 128
#define MAXB 32768

// ---- smem layout (bytes) ----
#define OFF_PERM 0
#define OFF_B1   512
#define OFF_B2   1536
#define OFF_C1   2560
#define OFF_A    3584
#define ASTRIDE  528                        // 256 halfs + pad (16B-mult, odd/16 -> conflict-free)
#define OFF_BB   (OFF_A + 128*ASTRIDE)      // 71168
#define BSTRIDE  80                         // 32 halfs payload + pad
#define BPLANE   20480
#define BLO      20480
#define BBUF     40960
#define SMEM_BYTES (OFF_BB + 2*BBUF)        // 153088

// ---------------- device scratch ----------------------------------------------
__device__ int g_cursor[NE];
__device__ int g_perm[NE * MAXB];
__device__ __align__(16) __half g_w1h[NE * DF * DF];
__device__ __align__(16) __half g_w1l[NE * DF * DF];
__device__ __align__(16) __half g_w2h[NE * DF * DF];
__device__ __align__(16) __half g_w2l[NE * DF * DF];

__device__ __forceinline__ int expert_of(float t) {
    int e = (int)(t * 8.0f);
    if (e > NE - 1) e = NE - 1;
    if (e < 0) e = 0;
    return e;
}

// ---- weight pre-split (fp32 -> fp16 hi + fp16 lo), also zeroes cursors --------
__global__ void k_wsplit(const float* __restrict__ W1, const float* __restrict__ W2) {
    if (blockIdx.x == 0 && threadIdx.x < NE) g_cursor[threadIdx.x] = 0;
    int v = (blockIdx.x * blockDim.x + threadIdx.x) * 4;
    float4 a = *(const float4*)(W1 + v);
    float4 b = *(const float4*)(W2 + v);
    __half h;
    __half2 hh, ll;
    h = __float2half_rn(a.x); hh.x = h; ll.x = __float2half_rn(a.x - __half2float(h));
    h = __float2half_rn(a.y); hh.y = h; ll.y = __float2half_rn(a.y - __half2float(h));
    *(__half2*)(g_w1h + v) = hh; *(__half2*)(g_w1l + v) = ll;
    h = __float2half_rn(a.z); hh.x = h; ll.x = __float2half_rn(a.z - __half2float(h));
    h = __float2half_rn(a.w); hh.y = h; ll.y = __float2half_rn(a.w - __half2float(h));
    *(__half2*)(g_w1h + v + 2) = hh; *(__half2*)(g_w1l + v + 2) = ll;
    h = __float2half_rn(b.x); hh.x = h; ll.x = __float2half_rn(b.x - __half2float(h));
    h = __float2half_rn(b.y); hh.y = h; ll.y = __float2half_rn(b.y - __half2float(h));
    *(__half2*)(g_w2h + v) = hh; *(__half2*)(g_w2l + v) = ll;
    h = __float2half_rn(b.z); hh.x = h; ll.x = __float2half_rn(b.z - __half2float(h));
    h = __float2half_rn(b.w); hh.y = h; ll.y = __float2half_rn(b.w - __half2float(h));
    *(__half2*)(g_w2h + v + 2) = hh; *(__half2*)(g_w2l + v + 2) = ll;
}

// ---- scatter into per-expert fixed regions ------------------------------------
__global__ void k_scatter(const float* __restrict__ t, int B) {
    __shared__ int h[NE], bb[NE];
    if (threadIdx.x < NE) h[threadIdx.x] = 0;
    __syncthreads();
    int i = blockIdx.x * blockDim.x + threadIdx.x;
    int e = 0, r = 0;
    bool valid = (i < B);
    if (valid) { e = expert_of(t[i]); r = atomicAdd(&h[e], 1); }
    __syncthreads();
    if (threadIdx.x < NE && h[threadIdx.x]) bb[threadIdx.x] = atomicAdd(&g_cursor[threadIdx.x], h[threadIdx.x]);
    __syncthreads();
    if (valid) g_perm[e * MAXB + bb[e] + r] = i;
}

// ---------------- helpers -------------------------------------------------------
__device__ __forceinline__ float sigmf(float x) { return 1.0f / (1.0f + expf(-x)); }
__device__ __forceinline__ float tanh_fast(float x) {
    x = fminf(fmaxf(x, -10.0f), 10.0f);
    float t = __expf(2.0f * x);
    return __fdividef(t - 1.0f, t + 1.0f);
}

__device__ __forceinline__ void ldsm4(uint32_t* r, uint32_t addr) {
    asm volatile("ldmatrix.sync.aligned.m8n8.x4.shared.b16 {%0,%1,%2,%3}, [%4];"
        : "=r"(r[0]), "=r"(r[1]), "=r"(r[2]), "=r"(r[3]) : "r"(addr));
}
__device__ __forceinline__ void mma_f16(float* d, const uint32_t* a, const uint32_t* b) {
    asm volatile("mma.sync.aligned.m16n8k16.row.col.f32.f16.f16.f32 "
        "{%0,%1,%2,%3}, {%4,%5,%6,%7}, {%8,%9}, {%0,%1,%2,%3};"
        : "+f"(d[0]), "+f"(d[1]), "+f"(d[2]), "+f"(d[3])
        : "r"(a[0]), "r"(a[1]), "r"(a[2]), "r"(a[3]), "r"(b[0]), "r"(b[1]));
}

// cp.async one 32-k chunk (hi+lo planes) into buffer `buf`, commit as one group
__device__ __forceinline__ void issue_chunk(uint32_t su, int buf,
                                            const __half* Wh, const __half* Wl,
                                            int kc, int tid) {
#pragma unroll
    for (int u = 0; u < 4; u++) {
        int v = tid + 256 * u;          // 0..1023
        int n = v >> 2, q = v & 3;
        uint32_t dst = su + OFF_BB + buf * BBUF + n * BSTRIDE + q * 16;
        const __half* s1 = Wh + (size_t)n * DF + kc * 32 + q * 8;
        const __half* s2 = Wl + (size_t)n * DF + kc * 32 + q * 8;
        asm volatile("cp.async.cg.shared.global [%0], [%1], 16;" :: "r"(dst), "l"(s1) : "memory");
        asm volatile("cp.async.cg.shared.global [%0], [%1], 16;" :: "r"(dst + BLO), "l"(s2) : "memory");
    }
    asm volatile("cp.async.commit_group;" ::: "memory");
}

// GEMM mainloop body (prologue chunks 0,1 already issued by caller)
__device__ __forceinline__ void gemm256(uint32_t su, const __half* Wh, const __half* Wl,
                                        float (&acc)[2][16][4], int lane, int wm, int wn, int tid) {
    uint32_t aBase = su + OFF_A
        + (uint32_t)(wm * 32 + ((lane >> 3) & 1) * 8 + (lane & 7)) * ASTRIDE
        + (uint32_t)(lane >> 4) * 16;
    uint32_t bLane = (uint32_t)(((lane & 7) + (lane >> 4) * 8) * BSTRIDE + ((lane >> 3) & 1) * 16);

    for (int kc = 0; kc < 8; kc++) {
        if (kc < 7) { asm volatile("cp.async.wait_group 1;" ::: "memory"); }
        else        { asm volatile("cp.async.wait_group 0;" ::: "memory"); }
        __syncthreads();
        uint32_t bBuf = su + OFF_BB + (kc & 1) * BBUF + bLane + (uint32_t)(wn * 128) * BSTRIDE;
#pragma unroll
        for (int ks = 0; ks < 2; ks++) {
            uint32_t aAddr = aBase + (uint32_t)(kc * 32 + ks * 16) * 2;
            uint32_t a0[4], a1[4];
            ldsm4(a0, aAddr);
            ldsm4(a1, aAddr + 16 * ASTRIDE);
            uint32_t bk = bBuf + ks * 32;
#pragma unroll
            for (int nt = 0; nt < 16; nt += 2) {
                uint32_t bh[4], bl[4];
                uint32_t baddr = bk + (uint32_t)(nt * 8) * BSTRIDE;
                ldsm4(bh, baddr);
                ldsm4(bl, baddr + BLO);
                mma_f16(acc[0][nt],     a0, bh + 0);
                mma_f16(acc[1][nt],     a1, bh + 0);
                mma_f16(acc[0][nt + 1], a0, bh + 2);
                mma_f16(acc[1][nt + 1], a1, bh + 2);
                mma_f16(acc[0][nt],     a0, bl + 0);
                mma_f16(acc[1][nt],     a1, bl + 0);
                mma_f16(acc[0][nt + 1], a0, bl + 2);
                mma_f16(acc[1][nt + 1], a1, bl + 2);
            }
        }
        __syncthreads();
        if (kc < 6) issue_chunk(su, kc & 1, Wh, Wl, kc + 2, tid);
    }
}

// ---------------- main fused MoE kernel ----------------------------------------
__global__ __launch_bounds__(256, 1) void k_moe(
    const float* __restrict__ y,
    const float* __restrict__ b1, const float* __restrict__ b2,
    const float* __restrict__ scales,
    const float* __restrict__ shifta, const float* __restrict__ shiftb,
    float* __restrict__ out)
{
    extern __shared__ char smem[];
    const int tid  = threadIdx.x;
    const int lane = tid & 31;
    const int wid  = tid >> 5;
    const int wm   = wid & 3;
    const int wn   = wid >> 2;

    // ---- block -> (expert, tile) ------------------------------------------
    int bid = blockIdx.x, e = 0, local = -1, acc_t = 0, cnt_e = 0;
#pragma unroll
    for (int q = 0; q < NE; q++) {
        int c  = g_cursor[q];
        int nt = (c + TM - 1) / TM;
        if (local < 0 && bid < acc_t + nt) { e = q; local = bid - acc_t; cnt_e = c; }
        acc_t += nt;
    }
    if (local < 0) return;
    int base = local * TM;
    int rows = cnt_e - base;
    if (rows > TM) rows = TM;

    uint32_t su;
    asm("{ .reg .u64 t; cvta.to.shared.u64 t, %1; cvt.u32.u64 %0, t; }" : "=r"(su) : "l"(smem));

    int*   sPerm = (int*)(smem + OFF_PERM);
    float* sB1   = (float*)(smem + OFF_B1);
    float* sB2   = (float*)(smem + OFF_B2);
    float* sC1   = (float*)(smem + OFF_C1);

    if (tid < TM) sPerm[tid] = (tid < rows) ? g_perm[e * MAXB + base + tid] : g_perm[e * MAXB + base];
    float sa = sigmf(shifta[0]);
    float sb = sigmf(shiftb[0]);
    float cy = 0.5f * (sb - sa);
    sB1[tid] = b1[e * DF + tid];
    sB2[tid] = b2[e * DF + tid];
    sC1[tid] = 0.5f * (sb + sa) * sigmf(scales[tid]);
    __syncthreads();

    const __half* W1h = g_w1h + (size_t)e * DF * DF;
    const __half* W1l = g_w1l + (size_t)e * DF * DF;
    const __half* W2h = g_w2h + (size_t)e * DF * DF;
    const __half* W2l = g_w2l + (size_t)e * DF * DF;

    // prologue W1 chunks first so they overlap the A gather
    issue_chunk(su, 0, W1h, W1l, 0, tid);
    issue_chunk(su, 1, W1h, W1l, 1, tid);

    // ---- gather Y rows -> A (fp16, single plane) ---------------------------
#pragma unroll 4
    for (int u = 0; u < 32; u++) {
        int v = tid + 256 * u;
        int r = v >> 6, q = v & 63;
        float4 d = *(const float4*)(y + (size_t)sPerm[r] * DF + q * 4);
        uint32_t off = (uint32_t)r * ASTRIDE + q * 8;
        *(__half2*)(smem + OFF_A + off)     = __floats2half2_rn(d.x, d.y);
        *(__half2*)(smem + OFF_A + off + 4) = __floats2half2_rn(d.z, d.w);
    }

    float acc[2][16][4];
#pragma unroll
    for (int i = 0; i < 2; i++)
#pragma unroll
        for (int j = 0; j < 16; j++)
#pragma unroll
            for (int c = 0; c < 4; c++) acc[i][j][c] = 0.0f;

    // =================== GEMM1 ==============================================
    gemm256(su, W1h, W1l, acc, lane, wm, wn, tid);

    // prologue W2 chunks (overlap H conversion)
    issue_chunk(su, 0, W2h, W2l, 0, tid);
    issue_chunk(su, 1, W2h, W2l, 1, tid);

    // ---- H = tanh(acc + b1) -> overwrite A (own rows only) -----------------
#pragma unroll
    for (int mt = 0; mt < 2; mt++)
#pragma unroll
        for (int sub = 0; sub < 2; sub++) {
            int m = wm * 32 + mt * 16 + sub * 8 + (lane >> 2);
#pragma unroll
            for (int nt = 0; nt < 16; nt++) {
                int n = wn * 128 + nt * 8 + (lane & 3) * 2;
                float h0 = tanh_fast(acc[mt][nt][sub * 2 + 0] + sB1[n]);
                float h1 = tanh_fast(acc[mt][nt][sub * 2 + 1] + sB1[n + 1]);
                *(__half2*)(smem + OFF_A + (uint32_t)m * ASTRIDE + n * 2) = __floats2half2_rn(h0, h1);
            }
        }

#pragma unroll
    for (int i = 0; i < 2; i++)
#pragma unroll
        for (int j = 0; j < 16; j++)
#pragma unroll
            for (int c = 0; c < 4; c++) acc[i][j][c] = 0.0f;

    // =================== GEMM2 ==============================================
    gemm256(su, W2h, W2l, acc, lane, wm, wn, tid);

    // ---- epilogue: out = c1*(acc + b2) + cy*y, scattered --------------------
#pragma unroll
    for (int mt = 0; mt < 2; mt++)
#pragma unroll
        for (int sub = 0; sub < 2; sub++) {
            int m = wm * 32 + mt * 16 + sub * 8 + (lane >> 2);
            if (m < rows) {
                int row = sPerm[m];
#pragma unroll
                for (int nt = 0; nt < 16; nt++) {
                    int n = wn * 128 + nt * 8 + (lane & 3) * 2;
                    float2 yv = *(const float2*)(y + (size_t)row * DF + n);
                    float2 o;
                    o.x = sC1[n]     * (acc[mt][nt][sub * 2 + 0] + sB2[n])     + cy * yv.x;
                    o.y = sC1[n + 1] * (acc[mt][nt][sub * 2 + 1] + sB2[n + 1]) + cy * yv.y;
                    *(float2*)(out + (size_t)row * DF + n) = o;
                }
            }
        }
}

// ---------------- launcher ------------------------------------------------------
extern "C" void kernel_launch(void* const* d_in, const int* in_sizes, int n_in,
                              void* d_out, int out_size)
{
    const float* t      = (const float*)d_in[0];
    const float* y      = (const float*)d_in[1];
    const float* W1     = (const float*)d_in[2];
    const float* b1     = (const float*)d_in[3];
    const float* W2     = (const float*)d_in[4];
    const float* b2     = (const float*)d_in[5];
    const float* scales = (const float*)d_in[6];
    const float* sha    = (const float*)d_in[7];
    const float* shb    = (const float*)d_in[8];
    float* out = (float*)d_out;
    int B = in_sizes[0];

    k_wsplit<<<NE * DF * DF / 4 / 256, 256>>>(W1, W2);   // 512 blocks; also zeroes cursors
    k_scatter<<<(B + 255) / 256, 256>>>(t, B);

    cudaFuncSetAttribute(k_moe, cudaFuncAttributeMaxDynamicSharedMemorySize, SMEM_BYTES);
    int grid = (B + TM - 1) / TM + NE;
    k_moe<<<grid, 256, SMEM_BYTES>>>(y, b1, b2, scales, sha, shb, out);
}

// round 5
// speedup vs baseline: 4.2697x; 1.3542x over previous
#include <cuda_runtime.h>
#include <cuda_fp16.h>
#include <stdint.h>
#include <math.h>

#define DF 256
#define NE 8
#define TM 128
#define MAXB 32768

// ---- smem layout (bytes) ----
#define OFF_PERM 0
#define OFF_B1   512
#define OFF_B2   1536
#define OFF_C1   2560
#define OFF_A    3584
#define ASTRIDE  528                        // 256 halfs + pad (conflict-free LDSM)
#define OFF_BB   (OFF_A + 128*ASTRIDE)      // 71168
#define BSTRIDE  80                         // 32 halfs payload + pad
#define BBUF     20480                      // single fp16 plane per buffer
#define SMEM_BYTES (OFF_BB + 2*BBUF)        // 112128

// ---------------- device scratch ----------------------------------------------
__device__ int g_cursor[NE];
__device__ int g_perm[NE * MAXB];
__device__ __align__(16) __half g_w1[NE * DF * DF];
__device__ __align__(16) __half g_w2[NE * DF * DF];

__device__ __forceinline__ int expert_of(float t) {
    int e = (int)(t * 8.0f);
    if (e > NE - 1) e = NE - 1;
    if (e < 0) e = 0;
    return e;
}

// ---- weight fp32 -> fp16 prep; also zeroes cursors ------------------------------
__global__ void k_wprep(const float* __restrict__ W1, const float* __restrict__ W2) {
    if (blockIdx.x == 0 && threadIdx.x < NE) g_cursor[threadIdx.x] = 0;
    int v = (blockIdx.x * blockDim.x + threadIdx.x) * 4;
    float4 a = *(const float4*)(W1 + v);
    float4 b = *(const float4*)(W2 + v);
    __half2 p0 = __floats2half2_rn(a.x, a.y);
    __half2 p1 = __floats2half2_rn(a.z, a.w);
    *(__half2*)(g_w1 + v)     = p0;
    *(__half2*)(g_w1 + v + 2) = p1;
    p0 = __floats2half2_rn(b.x, b.y);
    p1 = __floats2half2_rn(b.z, b.w);
    *(__half2*)(g_w2 + v)     = p0;
    *(__half2*)(g_w2 + v + 2) = p1;
}

// ---- scatter into per-expert fixed regions --------------------------------------
__global__ void k_scatter(const float* __restrict__ t, int B) {
    __shared__ int h[NE], bb[NE];
    if (threadIdx.x < NE) h[threadIdx.x] = 0;
    __syncthreads();
    int i = blockIdx.x * blockDim.x + threadIdx.x;
    int e = 0, r = 0;
    bool valid = (i < B);
    if (valid) { e = expert_of(t[i]); r = atomicAdd(&h[e], 1); }
    __syncthreads();
    if (threadIdx.x < NE && h[threadIdx.x]) bb[threadIdx.x] = atomicAdd(&g_cursor[threadIdx.x], h[threadIdx.x]);
    __syncthreads();
    if (valid) g_perm[e * MAXB + bb[e] + r] = i;
}

// ---------------- helpers ----------------------------------------------------------
__device__ __forceinline__ float sigmf(float x) { return 1.0f / (1.0f + expf(-x)); }
__device__ __forceinline__ float tanh_fast(float x) {
    x = fminf(fmaxf(x, -10.0f), 10.0f);
    float t = __expf(2.0f * x);
    return __fdividef(t - 1.0f, t + 1.0f);
}

__device__ __forceinline__ void ldsm4(uint32_t* r, uint32_t addr) {
    asm volatile("ldmatrix.sync.aligned.m8n8.x4.shared.b16 {%0,%1,%2,%3}, [%4];"
        : "=r"(r[0]), "=r"(r[1]), "=r"(r[2]), "=r"(r[3]) : "r"(addr));
}
__device__ __forceinline__ void mma_f16(float* d, const uint32_t* a, const uint32_t* b) {
    asm volatile("mma.sync.aligned.m16n8k16.row.col.f32.f16.f16.f32 "
        "{%0,%1,%2,%3}, {%4,%5,%6,%7}, {%8,%9}, {%0,%1,%2,%3};"
        : "+f"(d[0]), "+f"(d[1]), "+f"(d[2]), "+f"(d[3])
        : "r"(a[0]), "r"(a[1]), "r"(a[2]), "r"(a[3]), "r"(b[0]), "r"(b[1]));
}

// cp.async one 32-k chunk (single fp16 plane) into buffer `buf`
__device__ __forceinline__ void issue_chunk(uint32_t su, int buf,
                                            const __half* W, int kc, int tid) {
#pragma unroll
    for (int u = 0; u < 4; u++) {
        int v = tid + 256 * u;          // 0..1023 16B-lines
        int n = v >> 2, q = v & 3;
        uint32_t dst = su + OFF_BB + buf * BBUF + n * BSTRIDE + q * 16;
        const __half* s = W + (size_t)n * DF + kc * 32 + q * 8;
        asm volatile("cp.async.cg.shared.global [%0], [%1], 16;" :: "r"(dst), "l"(s) : "memory");
    }
    asm volatile("cp.async.commit_group;" ::: "memory");
}

// GEMM mainloop body (prologue chunks 0,1 already issued by caller)
__device__ __forceinline__ void gemm256(uint32_t su, const __half* W,
                                        float (&acc)[2][16][4], int lane, int wm, int wn, int tid) {
    uint32_t aBase = su + OFF_A
        + (uint32_t)(wm * 32 + ((lane >> 3) & 1) * 8 + (lane & 7)) * ASTRIDE
        + (uint32_t)(lane >> 4) * 16;
    uint32_t bLane = (uint32_t)(((lane & 7) + (lane >> 4) * 8) * BSTRIDE + ((lane >> 3) & 1) * 16);

    for (int kc = 0; kc < 8; kc++) {
        if (kc < 7) { asm volatile("cp.async.wait_group 1;" ::: "memory"); }
        else        { asm volatile("cp.async.wait_group 0;" ::: "memory"); }
        __syncthreads();
        uint32_t bBuf = su + OFF_BB + (kc & 1) * BBUF + bLane + (uint32_t)(wn * 128) * BSTRIDE;
#pragma unroll
        for (int ks = 0; ks < 2; ks++) {
            uint32_t aAddr = aBase + (uint32_t)(kc * 32 + ks * 16) * 2;
            uint32_t a0[4], a1[4];
            ldsm4(a0, aAddr);
            ldsm4(a1, aAddr + 16 * ASTRIDE);
            uint32_t bk = bBuf + ks * 32;
#pragma unroll
            for (int nt = 0; nt < 16; nt += 2) {
                uint32_t bh[4];
                ldsm4(bh, bk + (uint32_t)(nt * 8) * BSTRIDE);
                mma_f16(acc[0][nt],     a0, bh + 0);
                mma_f16(acc[1][nt],     a1, bh + 0);
                mma_f16(acc[0][nt + 1], a0, bh + 2);
                mma_f16(acc[1][nt + 1], a1, bh + 2);
            }
        }
        __syncthreads();
        if (kc < 6) issue_chunk(su, kc & 1, W, kc + 2, tid);
    }
}

// ---------------- main fused MoE kernel --------------------------------------------
__global__ __launch_bounds__(256, 1) void k_moe(
    const float* __restrict__ y,
    const float* __restrict__ b1, const float* __restrict__ b2,
    const float* __restrict__ scales,
    const float* __restrict__ shifta, const float* __restrict__ shiftb,
    float* __restrict__ out)
{
    extern __shared__ char smem[];
    const int tid  = threadIdx.x;
    const int lane = tid & 31;
    const int wid  = tid >> 5;
    const int wm   = wid & 3;
    const int wn   = wid >> 2;

    // ---- block -> (expert, tile) --------------------------------------------
    int bid = blockIdx.x, e = 0, local = -1, acc_t = 0, cnt_e = 0;
#pragma unroll
    for (int q = 0; q < NE; q++) {
        int c  = g_cursor[q];
        int nt = (c + TM - 1) / TM;
        if (local < 0 && bid < acc_t + nt) { e = q; local = bid - acc_t; cnt_e = c; }
        acc_t += nt;
    }
    if (local < 0) return;
    int base = local * TM;
    int rows = cnt_e - base;
    if (rows > TM) rows = TM;

    uint32_t su;
    asm("{ .reg .u64 t; cvta.to.shared.u64 t, %1; cvt.u32.u64 %0, t; }" : "=r"(su) : "l"(smem));

    int*   sPerm = (int*)(smem + OFF_PERM);
    float* sB1   = (float*)(smem + OFF_B1);
    float* sB2   = (float*)(smem + OFF_B2);
    float* sC1   = (float*)(smem + OFF_C1);

    if (tid < TM) sPerm[tid] = (tid < rows) ? g_perm[e * MAXB + base + tid] : g_perm[e * MAXB + base];
    float sa = sigmf(shifta[0]);
    float sb = sigmf(shiftb[0]);
    float cy = 0.5f * (sb - sa);
    sB1[tid] = b1[e * DF + tid];
    sB2[tid] = b2[e * DF + tid];
    sC1[tid] = 0.5f * (sb + sa) * sigmf(scales[tid]);
    __syncthreads();

    const __half* W1e = g_w1 + (size_t)e * DF * DF;
    const __half* W2e = g_w2 + (size_t)e * DF * DF;

    // prologue W1 chunks first so they overlap the A gather
    issue_chunk(su, 0, W1e, 0, tid);
    issue_chunk(su, 1, W1e, 1, tid);

    // ---- gather Y rows -> A (fp16) -------------------------------------------
#pragma unroll 4
    for (int u = 0; u < 32; u++) {
        int v = tid + 256 * u;
        int r = v >> 6, q = v & 63;
        float4 d = *(const float4*)(y + (size_t)sPerm[r] * DF + q * 4);
        uint32_t off = (uint32_t)r * ASTRIDE + q * 8;
        *(__half2*)(smem + OFF_A + off)     = __floats2half2_rn(d.x, d.y);
        *(__half2*)(smem + OFF_A + off + 4) = __floats2half2_rn(d.z, d.w);
    }

    float acc[2][16][4];
#pragma unroll
    for (int i = 0; i < 2; i++)
#pragma unroll
        for (int j = 0; j < 16; j++)
#pragma unroll
            for (int c = 0; c < 4; c++) acc[i][j][c] = 0.0f;

    // =================== GEMM1 ================================================
    gemm256(su, W1e, acc, lane, wm, wn, tid);

    // prologue W2 chunks (overlap H conversion)
    issue_chunk(su, 0, W2e, 0, tid);
    issue_chunk(su, 1, W2e, 1, tid);

    // ---- H = tanh(acc + b1) -> overwrite A (own rows only) -------------------
#pragma unroll
    for (int mt = 0; mt < 2; mt++)
#pragma unroll
        for (int sub = 0; sub < 2; sub++) {
            int m = wm * 32 + mt * 16 + sub * 8 + (lane >> 2);
#pragma unroll
            for (int nt = 0; nt < 16; nt++) {
                int n = wn * 128 + nt * 8 + (lane & 3) * 2;
                float h0 = tanh_fast(acc[mt][nt][sub * 2 + 0] + sB1[n]);
                float h1 = tanh_fast(acc[mt][nt][sub * 2 + 1] + sB1[n + 1]);
                *(__half2*)(smem + OFF_A + (uint32_t)m * ASTRIDE + n * 2) = __floats2half2_rn(h0, h1);
            }
        }

#pragma unroll
    for (int i = 0; i < 2; i++)
#pragma unroll
        for (int j = 0; j < 16; j++)
#pragma unroll
            for (int c = 0; c < 4; c++) acc[i][j][c] = 0.0f;

    // =================== GEMM2 ================================================
    gemm256(su, W2e, acc, lane, wm, wn, tid);

    // ---- epilogue: out = c1*(acc + b2) + cy*y, scattered ----------------------
#pragma unroll
    for (int mt = 0; mt < 2; mt++)
#pragma unroll
        for (int sub = 0; sub < 2; sub++) {
            int m = wm * 32 + mt * 16 + sub * 8 + (lane >> 2);
            if (m < rows) {
                int row = sPerm[m];
#pragma unroll
                for (int nt = 0; nt < 16; nt++) {
                    int n = wn * 128 + nt * 8 + (lane & 3) * 2;
                    float2 yv = *(const float2*)(y + (size_t)row * DF + n);
                    float2 o;
                    o.x = sC1[n]     * (acc[mt][nt][sub * 2 + 0] + sB2[n])     + cy * yv.x;
                    o.y = sC1[n + 1] * (acc[mt][nt][sub * 2 + 1] + sB2[n + 1]) + cy * yv.y;
                    *(float2*)(out + (size_t)row * DF + n) = o;
                }
            }
        }
}

// ---------------- launcher ------------------------------------------------------
extern "C" void kernel_launch(void* const* d_in, const int* in_sizes, int n_in,
                              void* d_out, int out_size)
{
    const float* t      = (const float*)d_in[0];
    const float* y      = (const float*)d_in[1];
    const float* W1     = (const float*)d_in[2];
    const float* b1     = (const float*)d_in[3];
    const float* W2     = (const float*)d_in[4];
    const float* b2     = (const float*)d_in[5];
    const float* scales = (const float*)d_in[6];
    const float* sha    = (const float*)d_in[7];
    const float* shb    = (const float*)d_in[8];
    float* out = (float*)d_out;
    int B = in_sizes[0];

    k_wprep<<<NE * DF * DF / 4 / 256, 256>>>(W1, W2);   // also zeroes cursors
    k_scatter<<<(B + 255) / 256, 256>>>(t, B);

    cudaFuncSetAttribute(k_moe, cudaFuncAttributeMaxDynamicSharedMemorySize, SMEM_BYTES);
    int grid = (B + TM - 1) / TM + NE;
    k_moe<<<grid, 256, SMEM_BYTES>>>(y, b1, b2, scales, sha, shb, out);
}

// round 6
// speedup vs baseline: 5.3427x; 1.2513x over previous
#include <cuda_runtime.h>
#include <cuda_fp16.h>
#include <stdint.h>
#include <math.h>

#define DF 256
#define NE 8
#define TM 128
#define MAXB 32768

// ---- smem layout (bytes) ----
#define OFF_PERM 0
#define OFF_B1   512
#define OFF_B2   1536
#define OFF_C1   2560
#define OFF_A    3584
#define ASTRIDE  528                        // 256 halfs + pad (conflict-free LDSM)
#define OFF_BB   (OFF_A + 128*ASTRIDE)      // 71168
#define BSTRIDE  80                         // 32 halfs payload + pad
#define BBUF     20480                      // single fp16 plane per buffer
#define SMEM_BYTES (OFF_BB + 2*BBUF)        // 112128

// ---------------- device scratch (zero-initialized at load) --------------------
__device__ int g_cursor[NE];
__device__ int g_done;
__device__ int g_perm[NE * MAXB];
__device__ __align__(16) __half g_w1[NE * DF * DF];
__device__ __align__(16) __half g_w2[NE * DF * DF];

__device__ __forceinline__ int expert_of(float t) {
    int e = (int)(t * 8.0f);
    if (e > NE - 1) e = NE - 1;
    if (e < 0) e = 0;
    return e;
}

// ---- merged prep: blocks [0,512) convert weights; blocks [512,..) scatter ------
// g_cursor is zero on entry (static init on first call; reset by k_moe afterwards)
__global__ void k_prep(const float* __restrict__ W1, const float* __restrict__ W2,
                       const float* __restrict__ t, int B) {
    if (blockIdx.x < 512) {
        int v = (blockIdx.x * blockDim.x + threadIdx.x) * 4;
        float4 a = *(const float4*)(W1 + v);
        float4 b = *(const float4*)(W2 + v);
        *(__half2*)(g_w1 + v)     = __floats2half2_rn(a.x, a.y);
        *(__half2*)(g_w1 + v + 2) = __floats2half2_rn(a.z, a.w);
        *(__half2*)(g_w2 + v)     = __floats2half2_rn(b.x, b.y);
        *(__half2*)(g_w2 + v + 2) = __floats2half2_rn(b.z, b.w);
    } else {
        __shared__ int h[NE], bb[NE];
        if (threadIdx.x < NE) h[threadIdx.x] = 0;
        __syncthreads();
        int i = (blockIdx.x - 512) * blockDim.x + threadIdx.x;
        int e = 0, r = 0;
        bool valid = (i < B);
        if (valid) { e = expert_of(t[i]); r = atomicAdd(&h[e], 1); }
        __syncthreads();
        if (threadIdx.x < NE && h[threadIdx.x])
            bb[threadIdx.x] = atomicAdd(&g_cursor[threadIdx.x], h[threadIdx.x]);
        __syncthreads();
        if (valid) g_perm[e * MAXB + bb[e] + r] = i;
    }
}

// ---------------- helpers ----------------------------------------------------------
__device__ __forceinline__ float sigmf(float x) { return 1.0f / (1.0f + expf(-x)); }
__device__ __forceinline__ float tanh_fast(float x) {
    x = fminf(fmaxf(x, -10.0f), 10.0f);
    float t = __expf(2.0f * x);
    return __fdividef(t - 1.0f, t + 1.0f);
}

__device__ __forceinline__ void ldsm4(uint32_t* r, uint32_t addr) {
    asm volatile("ldmatrix.sync.aligned.m8n8.x4.shared.b16 {%0,%1,%2,%3}, [%4];"
        : "=r"(r[0]), "=r"(r[1]), "=r"(r[2]), "=r"(r[3]) : "r"(addr));
}
__device__ __forceinline__ void mma_f16(float* d, const uint32_t* a, const uint32_t* b) {
    asm volatile("mma.sync.aligned.m16n8k16.row.col.f32.f16.f16.f32 "
        "{%0,%1,%2,%3}, {%4,%5,%6,%7}, {%8,%9}, {%0,%1,%2,%3};"
        : "+f"(d[0]), "+f"(d[1]), "+f"(d[2]), "+f"(d[3])
        : "r"(a[0]), "r"(a[1]), "r"(a[2]), "r"(a[3]), "r"(b[0]), "r"(b[1]));
}

// cp.async one 32-k weight chunk into buffer `buf`
__device__ __forceinline__ void issue_chunk(uint32_t su, int buf,
                                            const __half* W, int kc, int tid) {
#pragma unroll
    for (int u = 0; u < 4; u++) {
        int v = tid + 256 * u;
        int n = v >> 2, q = v & 3;
        uint32_t dst = su + OFF_BB + buf * BBUF + n * BSTRIDE + q * 16;
        const __half* s = W + (size_t)n * DF + kc * 32 + q * 8;
        asm volatile("cp.async.cg.shared.global [%0], [%1], 16;" :: "r"(dst), "l"(s) : "memory");
    }
    asm volatile("cp.async.commit_group;" ::: "memory");
}

// pack 4 floats -> 4 fp16 and store 8B to smem
__device__ __forceinline__ void sts_f16x4(uint32_t addr, float4 d) {
    __half2 p0 = __floats2half2_rn(d.x, d.y);
    __half2 p1 = __floats2half2_rn(d.z, d.w);
    uint32_t u0 = *reinterpret_cast<uint32_t*>(&p0);
    uint32_t u1 = *reinterpret_cast<uint32_t*>(&p1);
    asm volatile("st.shared.v2.b32 [%0], {%1,%2};" :: "r"(addr), "r"(u0), "r"(u1) : "memory");
}

// GEMM mainloop. If GATHER: also streams A (y rows) chunk kc+2 during MMA of kc.
// yr[u] = pointer to this thread's slice base in row u; aSts = smem dst base.
template<bool GATHER>
__device__ __forceinline__ void gemm256(uint32_t su, const __half* W,
                                        float (&acc)[2][16][4], int lane, int wm, int wn, int tid,
                                        const float* const* yr, uint32_t aSts) {
    uint32_t aBase = su + OFF_A
        + (uint32_t)(wm * 32 + ((lane >> 3) & 1) * 8 + (lane & 7)) * ASTRIDE
        + (uint32_t)(lane >> 4) * 16;
    uint32_t bLane = (uint32_t)(((lane & 7) + (lane >> 4) * 8) * BSTRIDE + ((lane >> 3) & 1) * 16);

    for (int kc = 0; kc < 8; kc++) {
        float4 stg[4];
        if (GATHER && kc < 6) {
#pragma unroll
            for (int u = 0; u < 4; u++) stg[u] = *(const float4*)(yr[u] + (kc + 2) * 32);
        }
        if (kc < 7) { asm volatile("cp.async.wait_group 1;" ::: "memory"); }
        else        { asm volatile("cp.async.wait_group 0;" ::: "memory"); }
        __syncthreads();
        uint32_t bBuf = su + OFF_BB + (kc & 1) * BBUF + bLane + (uint32_t)(wn * 128) * BSTRIDE;
#pragma unroll
        for (int ks = 0; ks < 2; ks++) {
            uint32_t aAddr = aBase + (uint32_t)(kc * 32 + ks * 16) * 2;
            uint32_t a0[4], a1[4];
            ldsm4(a0, aAddr);
            ldsm4(a1, aAddr + 16 * ASTRIDE);
            uint32_t bk = bBuf + ks * 32;
#pragma unroll
            for (int nt = 0; nt < 16; nt += 2) {
                uint32_t bh[4];
                ldsm4(bh, bk + (uint32_t)(nt * 8) * BSTRIDE);
                mma_f16(acc[0][nt],     a0, bh + 0);
                mma_f16(acc[1][nt],     a1, bh + 0);
                mma_f16(acc[0][nt + 1], a0, bh + 2);
                mma_f16(acc[1][nt + 1], a1, bh + 2);
            }
        }
        if (GATHER && kc < 6) {
#pragma unroll
            for (int u = 0; u < 4; u++)
                sts_f16x4(aSts + (uint32_t)u * 32 * ASTRIDE + (uint32_t)(kc + 2) * 64, stg[u]);
        }
        __syncthreads();
        if (kc < 6) issue_chunk(su, kc & 1, W, kc + 2, tid);
    }
}

// ---------------- main fused MoE kernel --------------------------------------------
__global__ __launch_bounds__(256, 1) void k_moe(
    const float* __restrict__ y,
    const float* __restrict__ b1, const float* __restrict__ b2,
    const float* __restrict__ scales,
    const float* __restrict__ shifta, const float* __restrict__ shiftb,
    float* __restrict__ out, int nGrid)
{
    extern __shared__ char smem[];
    const int tid  = threadIdx.x;
    const int lane = tid & 31;
    const int wid  = tid >> 5;
    const int wm   = wid & 3;
    const int wn   = wid >> 2;

    // ---- block -> (expert, tile) --------------------------------------------
    int bid = blockIdx.x, e = 0, local = -1, acc_t = 0, cnt_e = 0;
#pragma unroll
    for (int q = 0; q < NE; q++) {
        int c  = g_cursor[q];
        int nt = (c + TM - 1) / TM;
        if (local < 0 && bid < acc_t + nt) { e = q; local = bid - acc_t; cnt_e = c; }
        acc_t += nt;
    }

    if (local >= 0) {
        int base = local * TM;
        int rows = cnt_e - base;
        if (rows > TM) rows = TM;

        uint32_t su;
        asm("{ .reg .u64 t; cvta.to.shared.u64 t, %1; cvt.u32.u64 %0, t; }" : "=r"(su) : "l"(smem));

        int*   sPerm = (int*)(smem + OFF_PERM);
        float* sB1   = (float*)(smem + OFF_B1);
        float* sB2   = (float*)(smem + OFF_B2);
        float* sC1   = (float*)(smem + OFF_C1);

        if (tid < TM) sPerm[tid] = (tid < rows) ? g_perm[e * MAXB + base + tid] : g_perm[e * MAXB + base];
        float sa = sigmf(shifta[0]);
        float sb = sigmf(shiftb[0]);
        float cy = 0.5f * (sb - sa);
        sB1[tid] = b1[e * DF + tid];
        sB2[tid] = b2[e * DF + tid];
        sC1[tid] = 0.5f * (sb + sa) * sigmf(scales[tid]);
        __syncthreads();

        const __half* W1e = g_w1 + (size_t)e * DF * DF;
        const __half* W2e = g_w2 + (size_t)e * DF * DF;

        // prologue W1 chunks
        issue_chunk(su, 0, W1e, 0, tid);
        issue_chunk(su, 1, W1e, 1, tid);

        // per-thread gather slice: rows r(u) = (tid>>3) + 32u, float4-slot q = tid&7
        const float* yr[4];
        {
            int rb = tid >> 3, q = tid & 7;
#pragma unroll
            for (int u = 0; u < 4; u++)
                yr[u] = y + (size_t)sPerm[rb + 32 * u] * DF + q * 4;
        }
        uint32_t aSts = 0;
        {
            uint32_t su2;
            asm("{ .reg .u64 t; cvta.to.shared.u64 t, %1; cvt.u32.u64 %0, t; }" : "=r"(su2) : "l"(smem));
            aSts = su2 + OFF_A + (uint32_t)(tid >> 3) * ASTRIDE + (uint32_t)(tid & 7) * 8;
        }

        // gather A chunks 0,1 (prologue)
#pragma unroll
        for (int c = 0; c < 2; c++)
#pragma unroll
            for (int u = 0; u < 4; u++) {
                float4 d = *(const float4*)(yr[u] + c * 32);
                sts_f16x4(aSts + (uint32_t)u * 32 * ASTRIDE + (uint32_t)c * 64, d);
            }

        float acc[2][16][4];
#pragma unroll
        for (int i = 0; i < 2; i++)
#pragma unroll
            for (int j = 0; j < 16; j++)
#pragma unroll
                for (int c = 0; c < 4; c++) acc[i][j][c] = 0.0f;

        // =================== GEMM1 (gather-pipelined) =========================
        gemm256<true>(su, W1e, acc, lane, wm, wn, tid, yr, aSts);

        // prologue W2 chunks (overlap H conversion)
        issue_chunk(su, 0, W2e, 0, tid);
        issue_chunk(su, 1, W2e, 1, tid);

        // ---- H = tanh(acc + b1) -> overwrite A (own rows only) ---------------
#pragma unroll
        for (int mt = 0; mt < 2; mt++)
#pragma unroll
            for (int sub = 0; sub < 2; sub++) {
                int m = wm * 32 + mt * 16 + sub * 8 + (lane >> 2);
#pragma unroll
                for (int nt = 0; nt < 16; nt++) {
                    int n = wn * 128 + nt * 8 + (lane & 3) * 2;
                    float h0 = tanh_fast(acc[mt][nt][sub * 2 + 0] + sB1[n]);
                    float h1 = tanh_fast(acc[mt][nt][sub * 2 + 1] + sB1[n + 1]);
                    *(__half2*)(smem + OFF_A + (uint32_t)m * ASTRIDE + n * 2) = __floats2half2_rn(h0, h1);
                }
            }

#pragma unroll
        for (int i = 0; i < 2; i++)
#pragma unroll
            for (int j = 0; j < 16; j++)
#pragma unroll
                for (int c = 0; c < 4; c++) acc[i][j][c] = 0.0f;

        // =================== GEMM2 ============================================
        gemm256<false>(su, W2e, acc, lane, wm, wn, tid, yr, aSts);

        // ---- epilogue: out = c1*(acc + b2) + cy*y, scattered ------------------
        bool need_y = (cy != 0.0f);
#pragma unroll
        for (int mt = 0; mt < 2; mt++)
#pragma unroll
            for (int sub = 0; sub < 2; sub++) {
                int m = wm * 32 + mt * 16 + sub * 8 + (lane >> 2);
                if (m < rows) {
                    int row = sPerm[m];
#pragma unroll
                    for (int nt = 0; nt < 16; nt++) {
                        int n = wn * 128 + nt * 8 + (lane & 3) * 2;
                        float2 o;
                        o.x = sC1[n]     * (acc[mt][nt][sub * 2 + 0] + sB2[n]);
                        o.y = sC1[n + 1] * (acc[mt][nt][sub * 2 + 1] + sB2[n + 1]);
                        if (need_y) {
                            float2 yv = *(const float2*)(y + (size_t)row * DF + n);
                            o.x += cy * yv.x;
                            o.y += cy * yv.y;
                        }
                        *(float2*)(out + (size_t)row * DF + n) = o;
                    }
                }
            }
    }

    // ---- self-reset routing state for next graph replay ----------------------
    __syncthreads();
    if (tid == 0) {
        int old = atomicAdd(&g_done, 1);
        if (old == nGrid - 1) {
            for (int q = 0; q < NE; q++) g_cursor[q] = 0;
            g_done = 0;
            __threadfence();
        }
    }
}

// ---------------- launcher ------------------------------------------------------
extern "C" void kernel_launch(void* const* d_in, const int* in_sizes, int n_in,
                              void* d_out, int out_size)
{
    const float* t      = (const float*)d_in[0];
    const float* y      = (const float*)d_in[1];
    const float* W1     = (const float*)d_in[2];
    const float* b1     = (const float*)d_in[3];
    const float* W2     = (const float*)d_in[4];
    const float* b2     = (const float*)d_in[5];
    const float* scales = (const float*)d_in[6];
    const float* sha    = (const float*)d_in[7];
    const float* shb    = (const float*)d_in[8];
    float* out = (float*)d_out;
    int B = in_sizes[0];

    int nb = (B + 255) / 256;
    k_prep<<<512 + nb, 256>>>(W1, W2, t, B);

    cudaFuncSetAttribute(k_moe, cudaFuncAttributeMaxDynamicSharedMemorySize, SMEM_BYTES);
    int grid = (B + TM - 1) / TM + NE;
    k_moe<<<grid, 256, SMEM_BYTES>>>(y, b1, b2, scales, sha, shb, out, grid);
}

// round 7
// speedup vs baseline: 6.2533x; 1.1705x over previous
#include <cuda_runtime.h>
#include <cuda_fp16.h>
#include <stdint.h>
#include <math.h>

#define DF 256
#define NE 8
#define TM 128
#define NT 512
#define MAXB 32768

// ---- smem layout (bytes) ----
#define OFF_PERM 0
#define OFF_B1   512
#define OFF_B2   1536
#define OFF_C1   2560
#define OFF_A    3584
#define ASTRIDE  528                        // 256 halfs + pad (conflict-free LDSM)
#define OFF_BB   (OFF_A + 128*ASTRIDE)      // 71168
#define BSTRIDE  80                         // 32 halfs payload + pad
#define BBUF     20480                      // one fp16 chunk (256n x 32k)
#define SMEM_BYTES (OFF_BB + 3*BBUF)        // 132608  (3-slot ring)

// ---------------- device scratch (zero-initialized at load) --------------------
__device__ int g_cursor[NE];
__device__ int g_done;
__device__ int g_perm[NE * MAXB];
__device__ __align__(16) __half g_w1[NE * DF * DF];
__device__ __align__(16) __half g_w2[NE * DF * DF];

__device__ __forceinline__ int expert_of(float t) {
    int e = (int)(t * 8.0f);
    if (e > NE - 1) e = NE - 1;
    if (e < 0) e = 0;
    return e;
}

// ---- merged prep: blocks [0,512) convert weights; blocks [512,..) scatter ------
__global__ void k_prep(const float* __restrict__ W1, const float* __restrict__ W2,
                       const float* __restrict__ t, int B) {
    if (blockIdx.x < 512) {
        int v = (blockIdx.x * blockDim.x + threadIdx.x) * 4;
        float4 a = *(const float4*)(W1 + v);
        float4 b = *(const float4*)(W2 + v);
        *(__half2*)(g_w1 + v)     = __floats2half2_rn(a.x, a.y);
        *(__half2*)(g_w1 + v + 2) = __floats2half2_rn(a.z, a.w);
        *(__half2*)(g_w2 + v)     = __floats2half2_rn(b.x, b.y);
        *(__half2*)(g_w2 + v + 2) = __floats2half2_rn(b.z, b.w);
    } else {
        __shared__ int h[NE], bb[NE];
        if (threadIdx.x < NE) h[threadIdx.x] = 0;
        __syncthreads();
        int i = (blockIdx.x - 512) * blockDim.x + threadIdx.x;
        int e = 0, r = 0;
        bool valid = (i < B);
        if (valid) { e = expert_of(t[i]); r = atomicAdd(&h[e], 1); }
        __syncthreads();
        if (threadIdx.x < NE && h[threadIdx.x])
            bb[threadIdx.x] = atomicAdd(&g_cursor[threadIdx.x], h[threadIdx.x]);
        __syncthreads();
        if (valid) g_perm[e * MAXB + bb[e] + r] = i;
    }
}

// ---------------- helpers ----------------------------------------------------------
__device__ __forceinline__ float sigmf(float x) { return 1.0f / (1.0f + expf(-x)); }
__device__ __forceinline__ float tanh_fast(float x) {
    x = fminf(fmaxf(x, -10.0f), 10.0f);
    float t = __expf(2.0f * x);
    return __fdividef(t - 1.0f, t + 1.0f);
}

__device__ __forceinline__ void ldsm4(uint32_t* r, uint32_t addr) {
    asm volatile("ldmatrix.sync.aligned.m8n8.x4.shared.b16 {%0,%1,%2,%3}, [%4];"
        : "=r"(r[0]), "=r"(r[1]), "=r"(r[2]), "=r"(r[3]) : "r"(addr));
}
__device__ __forceinline__ void mma_f16(float* d, const uint32_t* a, const uint32_t* b) {
    asm volatile("mma.sync.aligned.m16n8k16.row.col.f32.f16.f16.f32 "
        "{%0,%1,%2,%3}, {%4,%5,%6,%7}, {%8,%9}, {%0,%1,%2,%3};"
        : "+f"(d[0]), "+f"(d[1]), "+f"(d[2]), "+f"(d[3])
        : "r"(a[0]), "r"(a[1]), "r"(a[2]), "r"(a[3]), "r"(b[0]), "r"(b[1]));
}

// cp.async one 32-k weight chunk (256n x 32k fp16) into ring slot `slot`
__device__ __forceinline__ void issue_chunk(uint32_t su, int slot,
                                            const __half* W, int kc, int tid) {
#pragma unroll
    for (int u = 0; u < 2; u++) {
        int v = tid + NT * u;               // 0..1023 16B-lines
        int n = v >> 2, q = v & 3;
        uint32_t dst = su + OFF_BB + slot * BBUF + n * BSTRIDE + q * 16;
        const __half* s = W + (size_t)n * DF + kc * 32 + q * 8;
        asm volatile("cp.async.cg.shared.global [%0], [%1], 16;" :: "r"(dst), "l"(s) : "memory");
    }
    asm volatile("cp.async.commit_group;" ::: "memory");
}

// pack 4 floats -> 4 fp16, 8B STS
__device__ __forceinline__ void sts_f16x4(uint32_t addr, float4 d) {
    __half2 p0 = __floats2half2_rn(d.x, d.y);
    __half2 p1 = __floats2half2_rn(d.z, d.w);
    uint32_t u0 = *reinterpret_cast<uint32_t*>(&p0);
    uint32_t u1 = *reinterpret_cast<uint32_t*>(&p1);
    asm volatile("st.shared.v2.b32 [%0], {%1,%2};" :: "r"(addr), "r"(u0), "r"(u1) : "memory");
}

// GEMM mainloop over 8 k-chunks; 3-slot B ring, ONE barrier per chunk.
// If GATHER: streams A (y rows) chunk kc+2 during MMA of chunk kc.
template<bool GATHER>
__device__ __forceinline__ void gemm256(uint32_t su, const __half* W,
                                        float (&acc)[2][8][4], int lane, int wm, int wn, int tid,
                                        const float* const* yr, uint32_t aSts) {
    uint32_t aBase = su + OFF_A
        + (uint32_t)(wm * 32 + ((lane >> 3) & 1) * 8 + (lane & 7)) * ASTRIDE
        + (uint32_t)(lane >> 4) * 16;
    uint32_t bLane = (uint32_t)(((lane & 7) + (lane >> 4) * 8) * BSTRIDE + ((lane >> 3) & 1) * 16)
                   + (uint32_t)(wn * 64) * BSTRIDE;

    for (int kc = 0; kc < 8; kc++) {
        float4 stg[2];
        if (GATHER && kc < 6) {
#pragma unroll
            for (int u = 0; u < 2; u++) stg[u] = *(const float4*)(yr[u] + (kc + 2) * 32);
        }
        if (kc < 7) { asm volatile("cp.async.wait_group 1;" ::: "memory"); }
        else        { asm volatile("cp.async.wait_group 0;" ::: "memory"); }
        __syncthreads();   // chunk kc readable by all; slot (kc+2)%3 free for overwrite
        if (kc < 6) issue_chunk(su, (kc + 2) % 3, W, kc + 2, tid);
        uint32_t bBuf = su + OFF_BB + (kc % 3) * BBUF + bLane;
#pragma unroll
        for (int ks = 0; ks < 2; ks++) {
            uint32_t aAddr = aBase + (uint32_t)(kc * 32 + ks * 16) * 2;
            uint32_t a0[4], a1[4];
            ldsm4(a0, aAddr);
            ldsm4(a1, aAddr + 16 * ASTRIDE);
            uint32_t bk = bBuf + ks * 32;
#pragma unroll
            for (int nt = 0; nt < 8; nt += 2) {
                uint32_t bh[4];
                ldsm4(bh, bk + (uint32_t)(nt * 8) * BSTRIDE);
                mma_f16(acc[0][nt],     a0, bh + 0);
                mma_f16(acc[1][nt],     a1, bh + 0);
                mma_f16(acc[0][nt + 1], a0, bh + 2);
                mma_f16(acc[1][nt + 1], a1, bh + 2);
            }
        }
        if (GATHER && kc < 6) {
#pragma unroll
            for (int u = 0; u < 2; u++)
                sts_f16x4(aSts + (uint32_t)u * 64 * ASTRIDE + (uint32_t)(kc + 2) * 64, stg[u]);
        }
    }
}

// ---------------- main fused MoE kernel --------------------------------------------
__global__ __launch_bounds__(NT, 1) void k_moe(
    const float* __restrict__ y,
    const float* __restrict__ b1, const float* __restrict__ b2,
    const float* __restrict__ scales,
    const float* __restrict__ shifta, const float* __restrict__ shiftb,
    float* __restrict__ out, int nGrid)
{
    extern __shared__ char smem[];
    const int tid  = threadIdx.x;
    const int lane = tid & 31;
    const int wid  = tid >> 5;
    const int wm   = wid & 3;     // 4 warps along M (32 rows each)
    const int wn   = wid >> 2;    // 4 warps along N (64 cols each)

    // ---- block -> (expert, tile) --------------------------------------------
    int bid = blockIdx.x, e = 0, local = -1, acc_t = 0, cnt_e = 0;
#pragma unroll
    for (int q = 0; q < NE; q++) {
        int c  = g_cursor[q];
        int nt = (c + TM - 1) / TM;
        if (local < 0 && bid < acc_t + nt) { e = q; local = bid - acc_t; cnt_e = c; }
        acc_t += nt;
    }

    if (local >= 0) {
        int base = local * TM;
        int rows = cnt_e - base;
        if (rows > TM) rows = TM;

        uint32_t su;
        asm("{ .reg .u64 t; cvta.to.shared.u64 t, %1; cvt.u32.u64 %0, t; }" : "=r"(su) : "l"(smem));

        int*   sPerm = (int*)(smem + OFF_PERM);
        float* sB1   = (float*)(smem + OFF_B1);
        float* sB2   = (float*)(smem + OFF_B2);
        float* sC1   = (float*)(smem + OFF_C1);

        if (tid < TM) sPerm[tid] = (tid < rows) ? g_perm[e * MAXB + base + tid] : g_perm[e * MAXB + base];
        float sa = sigmf(shifta[0]);
        float sb = sigmf(shiftb[0]);
        float cy = 0.5f * (sb - sa);
        if (tid < DF) {
            sB1[tid] = b1[e * DF + tid];
            sB2[tid] = b2[e * DF + tid];
            sC1[tid] = 0.5f * (sb + sa) * sigmf(scales[tid]);
        }
        __syncthreads();

        const __half* W1e = g_w1 + (size_t)e * DF * DF;
        const __half* W2e = g_w2 + (size_t)e * DF * DF;

        // prologue W1 chunks -> slots 0,1
        issue_chunk(su, 0, W1e, 0, tid);
        issue_chunk(su, 1, W1e, 1, tid);

        // per-thread gather slice: rows (tid>>3) and (tid>>3)+64, f4-slot tid&7
        const float* yr[2];
        {
            int rb = tid >> 3, q = tid & 7;
            yr[0] = y + (size_t)sPerm[rb] * DF + q * 4;
            yr[1] = y + (size_t)sPerm[rb + 64] * DF + q * 4;
        }
        uint32_t aSts = su + OFF_A + (uint32_t)(tid >> 3) * ASTRIDE + (uint32_t)(tid & 7) * 8;

        // gather A chunks 0,1 (prologue)
#pragma unroll
        for (int c = 0; c < 2; c++)
#pragma unroll
            for (int u = 0; u < 2; u++) {
                float4 d = *(const float4*)(yr[u] + c * 32);
                sts_f16x4(aSts + (uint32_t)u * 64 * ASTRIDE + (uint32_t)c * 64, d);
            }

        float acc[2][8][4];
#pragma unroll
        for (int i = 0; i < 2; i++)
#pragma unroll
            for (int j = 0; j < 8; j++)
#pragma unroll
                for (int c = 0; c < 4; c++) acc[i][j][c] = 0.0f;

        // =================== GEMM1 (gather-pipelined) =========================
        gemm256<true>(su, W1e, acc, lane, wm, wn, tid, yr, aSts);

        __syncthreads();   // all warps done reading ring before GEMM2 prologue overwrites
        issue_chunk(su, 0, W2e, 0, tid);
        issue_chunk(su, 1, W2e, 1, tid);

        // ---- H = tanh(acc + b1) -> overwrite A (own rows only) ---------------
#pragma unroll
        for (int mt = 0; mt < 2; mt++)
#pragma unroll
            for (int sub = 0; sub < 2; sub++) {
                int m = wm * 32 + mt * 16 + sub * 8 + (lane >> 2);
#pragma unroll
                for (int nt = 0; nt < 8; nt++) {
                    int n = wn * 64 + nt * 8 + (lane & 3) * 2;
                    float h0 = tanh_fast(acc[mt][nt][sub * 2 + 0] + sB1[n]);
                    float h1 = tanh_fast(acc[mt][nt][sub * 2 + 1] + sB1[n + 1]);
                    *(__half2*)(smem + OFF_A + (uint32_t)m * ASTRIDE + n * 2) = __floats2half2_rn(h0, h1);
                }
            }

#pragma unroll
        for (int i = 0; i < 2; i++)
#pragma unroll
            for (int j = 0; j < 8; j++)
#pragma unroll
                for (int c = 0; c < 4; c++) acc[i][j][c] = 0.0f;

        // =================== GEMM2 ============================================
        gemm256<false>(su, W2e, acc, lane, wm, wn, tid, yr, aSts);

        // ---- epilogue: out = c1*(acc + b2) (+ cy*y), scattered ----------------
        bool need_y = (cy != 0.0f);
#pragma unroll
        for (int mt = 0; mt < 2; mt++)
#pragma unroll
            for (int sub = 0; sub < 2; sub++) {
                int m = wm * 32 + mt * 16 + sub * 8 + (lane >> 2);
                if (m < rows) {
                    int row = sPerm[m];
#pragma unroll
                    for (int nt = 0; nt < 8; nt++) {
                        int n = wn * 64 + nt * 8 + (lane & 3) * 2;
                        float2 o;
                        o.x = sC1[n]     * (acc[mt][nt][sub * 2 + 0] + sB2[n]);
                        o.y = sC1[n + 1] * (acc[mt][nt][sub * 2 + 1] + sB2[n + 1]);
                        if (need_y) {
                            float2 yv = *(const float2*)(y + (size_t)row * DF + n);
                            o.x += cy * yv.x;
                            o.y += cy * yv.y;
                        }
                        *(float2*)(out + (size_t)row * DF + n) = o;
                    }
                }
            }
    }

    // ---- self-reset routing state for next graph replay ----------------------
    __syncthreads();
    if (tid == 0) {
        int old = atomicAdd(&g_done, 1);
        if (old == nGrid - 1) {
            for (int q = 0; q < NE; q++) g_cursor[q] = 0;
            g_done = 0;
            __threadfence();
        }
    }
}

// ---------------- launcher ------------------------------------------------------
extern "C" void kernel_launch(void* const* d_in, const int* in_sizes, int n_in,
                              void* d_out, int out_size)
{
    const float* t      = (const float*)d_in[0];
    const float* y      = (const float*)d_in[1];
    const float* W1     = (const float*)d_in[2];
    const float* b1     = (const float*)d_in[3];
    const float* W2     = (const float*)d_in[4];
    const float* b2     = (const float*)d_in[5];
    const float* scales = (const float*)d_in[6];
    const float* sha    = (const float*)d_in[7];
    const float* shb    = (const float*)d_in[8];
    float* out = (float*)d_out;
    int B = in_sizes[0];

    int nb = (B + 255) / 256;
    k_prep<<<512 + nb, 256>>>(W1, W2, t, B);

    cudaFuncSetAttribute(k_moe, cudaFuncAttributeMaxDynamicSharedMemorySize, SMEM_BYTES);
    int grid = (B + TM - 1) / TM + NE;
    k_moe<<<grid, NT, SMEM_BYTES>>>(y, b1, b2, scales, sha, shb, out, grid);
}

// round 8
// speedup vs baseline: 6.2870x; 1.0054x over previous
#include <cuda_runtime.h>
#include <cuda_fp16.h>
#include <stdint.h>
#include <math.h>

#define DF 256
#define NE 8
#define TM 64
#define NT 256
#define MAXB 32768

// ---- smem layout (bytes) ----
#define OFF_PERM 0
#define OFF_B1   512
#define OFF_B2   1536
#define OFF_C1   2560
#define OFF_A    3584
#define ASTRIDE  528                        // 256 halfs + pad (conflict-free LDSM)
#define OFF_BB   (OFF_A + 64*ASTRIDE)       // 37376
#define BSTRIDE  80                         // 32 halfs payload + pad
#define BBUF     20480                      // one fp16 chunk (256n x 32k)
#define SMEM_BYTES (OFF_BB + 3*BBUF)        // 98816 -> 2 CTAs/SM

// ---------------- device scratch (zero-initialized at load) --------------------
__device__ int g_cursor[NE];
__device__ int g_done;
__device__ int g_perm[NE * MAXB];
__device__ __align__(16) __half g_w1[NE * DF * DF];
__device__ __align__(16) __half g_w2[NE * DF * DF];

__device__ __forceinline__ int expert_of(float t) {
    int e = (int)(t * 8.0f);
    if (e > NE - 1) e = NE - 1;
    if (e < 0) e = 0;
    return e;
}

// ---- merged prep: blocks [0,512) convert weights; blocks [512,..) scatter ------
__global__ void k_prep(const float* __restrict__ W1, const float* __restrict__ W2,
                       const float* __restrict__ t, int B) {
    if (blockIdx.x < 512) {
        int v = (blockIdx.x * blockDim.x + threadIdx.x) * 4;
        float4 a = *(const float4*)(W1 + v);
        float4 b = *(const float4*)(W2 + v);
        *(__half2*)(g_w1 + v)     = __floats2half2_rn(a.x, a.y);
        *(__half2*)(g_w1 + v + 2) = __floats2half2_rn(a.z, a.w);
        *(__half2*)(g_w2 + v)     = __floats2half2_rn(b.x, b.y);
        *(__half2*)(g_w2 + v + 2) = __floats2half2_rn(b.z, b.w);
    } else {
        __shared__ int h[NE], bb[NE];
        if (threadIdx.x < NE) h[threadIdx.x] = 0;
        __syncthreads();
        int i = (blockIdx.x - 512) * blockDim.x + threadIdx.x;
        int e = 0, r = 0;
        bool valid = (i < B);
        if (valid) { e = expert_of(t[i]); r = atomicAdd(&h[e], 1); }
        __syncthreads();
        if (threadIdx.x < NE && h[threadIdx.x])
            bb[threadIdx.x] = atomicAdd(&g_cursor[threadIdx.x], h[threadIdx.x]);
        __syncthreads();
        if (valid) g_perm[e * MAXB + bb[e] + r] = i;
    }
}

// ---------------- helpers ----------------------------------------------------------
__device__ __forceinline__ float sigmf(float x) { return 1.0f / (1.0f + expf(-x)); }
__device__ __forceinline__ float tanh_approx(float x) {
    float r;
    asm("tanh.approx.f32 %0, %1;" : "=f"(r) : "f"(x));
    return r;
}

__device__ __forceinline__ void ldsm4(uint32_t* r, uint32_t addr) {
    asm volatile("ldmatrix.sync.aligned.m8n8.x4.shared.b16 {%0,%1,%2,%3}, [%4];"
        : "=r"(r[0]), "=r"(r[1]), "=r"(r[2]), "=r"(r[3]) : "r"(addr));
}
__device__ __forceinline__ void mma_f16(float* d, const uint32_t* a, const uint32_t* b) {
    asm volatile("mma.sync.aligned.m16n8k16.row.col.f32.f16.f16.f32 "
        "{%0,%1,%2,%3}, {%4,%5,%6,%7}, {%8,%9}, {%0,%1,%2,%3};"
        : "+f"(d[0]), "+f"(d[1]), "+f"(d[2]), "+f"(d[3])
        : "r"(a[0]), "r"(a[1]), "r"(a[2]), "r"(a[3]), "r"(b[0]), "r"(b[1]));
}

// cp.async one 32-k weight chunk (256n x 32k fp16) into ring slot `slot`
__device__ __forceinline__ void issue_chunk(uint32_t su, int slot,
                                            const __half* W, int kc, int tid) {
#pragma unroll
    for (int u = 0; u < 4; u++) {
        int v = tid + NT * u;               // 0..1023 16B-lines
        int n = v >> 2, q = v & 3;
        uint32_t dst = su + OFF_BB + slot * BBUF + n * BSTRIDE + q * 16;
        const __half* s = W + (size_t)n * DF + kc * 32 + q * 8;
        asm volatile("cp.async.cg.shared.global [%0], [%1], 16;" :: "r"(dst), "l"(s) : "memory");
    }
    asm volatile("cp.async.commit_group;" ::: "memory");
}

// pack 4 floats -> 4 fp16, 8B STS
__device__ __forceinline__ void sts_f16x4(uint32_t addr, float4 d) {
    __half2 p0 = __floats2half2_rn(d.x, d.y);
    __half2 p1 = __floats2half2_rn(d.z, d.w);
    uint32_t u0 = *reinterpret_cast<uint32_t*>(&p0);
    uint32_t u1 = *reinterpret_cast<uint32_t*>(&p1);
    asm volatile("st.shared.v2.b32 [%0], {%1,%2};" :: "r"(addr), "r"(u0), "r"(u1) : "memory");
}

// GEMM mainloop over 8 k-chunks; 3-slot B ring, ONE barrier per chunk.
// If GATHER: streams A (y rows) chunk kc+2 during MMA of chunk kc.
template<bool GATHER>
__device__ __forceinline__ void gemm256(uint32_t su, const __half* W,
                                        float (&acc)[2][8][4], int lane, int wm, int wn, int tid,
                                        const float* const* yr, uint32_t aSts) {
    uint32_t aBase = su + OFF_A
        + (uint32_t)(wm * 32 + ((lane >> 3) & 1) * 8 + (lane & 7)) * ASTRIDE
        + (uint32_t)(lane >> 4) * 16;
    uint32_t bLane = (uint32_t)(((lane & 7) + (lane >> 4) * 8) * BSTRIDE + ((lane >> 3) & 1) * 16)
                   + (uint32_t)(wn * 64) * BSTRIDE;

    for (int kc = 0; kc < 8; kc++) {
        float4 stg[2];
        if (GATHER && kc < 6) {
#pragma unroll
            for (int u = 0; u < 2; u++) stg[u] = *(const float4*)(yr[u] + (kc + 2) * 32);
        }
        if (kc < 7) { asm volatile("cp.async.wait_group 1;" ::: "memory"); }
        else        { asm volatile("cp.async.wait_group 0;" ::: "memory"); }
        __syncthreads();   // chunk kc readable by all; slot (kc+2)%3 free for overwrite
        if (kc < 6) issue_chunk(su, (kc + 2) % 3, W, kc + 2, tid);
        uint32_t bBuf = su + OFF_BB + (kc % 3) * BBUF + bLane;
#pragma unroll
        for (int ks = 0; ks < 2; ks++) {
            uint32_t aAddr = aBase + (uint32_t)(kc * 32 + ks * 16) * 2;
            uint32_t a0[4], a1[4];
            ldsm4(a0, aAddr);
            ldsm4(a1, aAddr + 16 * ASTRIDE);
            uint32_t bk = bBuf + ks * 32;
#pragma unroll
            for (int nt = 0; nt < 8; nt += 2) {
                uint32_t bh[4];
                ldsm4(bh, bk + (uint32_t)(nt * 8) * BSTRIDE);
                mma_f16(acc[0][nt],     a0, bh + 0);
                mma_f16(acc[1][nt],     a1, bh + 0);
                mma_f16(acc[0][nt + 1], a0, bh + 2);
                mma_f16(acc[1][nt + 1], a1, bh + 2);
            }
        }
        if (GATHER && kc < 6) {
#pragma unroll
            for (int u = 0; u < 2; u++)
                sts_f16x4(aSts + (uint32_t)u * 32 * ASTRIDE + (uint32_t)(kc + 2) * 64, stg[u]);
        }
    }
}

// ---------------- main fused MoE kernel --------------------------------------------
__global__ __launch_bounds__(NT, 2) void k_moe(
    const float* __restrict__ y,
    const float* __restrict__ b1, const float* __restrict__ b2,
    const float* __restrict__ scales,
    const float* __restrict__ shifta, const float* __restrict__ shiftb,
    float* __restrict__ out, int nGrid)
{
    extern __shared__ char smem[];
    const int tid  = threadIdx.x;
    const int lane = tid & 31;
    const int wid  = tid >> 5;
    const int wm   = wid & 1;     // 2 warps along M (32 rows each)
    const int wn   = wid >> 1;    // 4 warps along N (64 cols each)

    // ---- block -> (expert, tile) --------------------------------------------
    int bid = blockIdx.x, e = 0, local = -1, acc_t = 0, cnt_e = 0;
#pragma unroll
    for (int q = 0; q < NE; q++) {
        int c  = g_cursor[q];
        int nt = (c + TM - 1) / TM;
        if (local < 0 && bid < acc_t + nt) { e = q; local = bid - acc_t; cnt_e = c; }
        acc_t += nt;
    }

    if (local >= 0) {
        int base = local * TM;
        int rows = cnt_e - base;
        if (rows > TM) rows = TM;

        uint32_t su;
        asm("{ .reg .u64 t; cvta.to.shared.u64 t, %1; cvt.u32.u64 %0, t; }" : "=r"(su) : "l"(smem));

        int*   sPerm = (int*)(smem + OFF_PERM);
        float* sB1   = (float*)(smem + OFF_B1);
        float* sB2   = (float*)(smem + OFF_B2);
        float* sC1   = (float*)(smem + OFF_C1);

        if (tid < TM) sPerm[tid] = (tid < rows) ? g_perm[e * MAXB + base + tid] : g_perm[e * MAXB + base];
        float sa = sigmf(shifta[0]);
        float sb = sigmf(shiftb[0]);
        float cy = 0.5f * (sb - sa);
        sB1[tid] = b1[e * DF + tid];
        sB2[tid] = b2[e * DF + tid];
        sC1[tid] = 0.5f * (sb + sa) * sigmf(scales[tid]);
        __syncthreads();

        const __half* W1e = g_w1 + (size_t)e * DF * DF;
        const __half* W2e = g_w2 + (size_t)e * DF * DF;

        // prologue W1 chunks -> slots 0,1
        issue_chunk(su, 0, W1e, 0, tid);
        issue_chunk(su, 1, W1e, 1, tid);

        // per-thread gather slice: rows (tid>>3) and (tid>>3)+32, f4-slot tid&7
        const float* yr[2];
        {
            int rb = tid >> 3, q = tid & 7;
            yr[0] = y + (size_t)sPerm[rb] * DF + q * 4;
            yr[1] = y + (size_t)sPerm[rb + 32] * DF + q * 4;
        }
        uint32_t aSts = su + OFF_A + (uint32_t)(tid >> 3) * ASTRIDE + (uint32_t)(tid & 7) * 8;

        // gather A chunks 0,1 (prologue)
#pragma unroll
        for (int c = 0; c < 2; c++)
#pragma unroll
            for (int u = 0; u < 2; u++) {
                float4 d = *(const float4*)(yr[u] + c * 32);
                sts_f16x4(aSts + (uint32_t)u * 32 * ASTRIDE + (uint32_t)c * 64, d);
            }

        float acc[2][8][4];
#pragma unroll
        for (int i = 0; i < 2; i++)
#pragma unroll
            for (int j = 0; j < 8; j++)
#pragma unroll
                for (int c = 0; c < 4; c++) acc[i][j][c] = 0.0f;

        // =================== GEMM1 (gather-pipelined) =========================
        gemm256<true>(su, W1e, acc, lane, wm, wn, tid, yr, aSts);

        __syncthreads();   // ring fully read before GEMM2 prologue overwrites
        issue_chunk(su, 0, W2e, 0, tid);
        issue_chunk(su, 1, W2e, 1, tid);

        // ---- H = tanh(acc + b1) -> overwrite A (own rows only) ---------------
#pragma unroll
        for (int mt = 0; mt < 2; mt++)
#pragma unroll
            for (int sub = 0; sub < 2; sub++) {
                int m = wm * 32 + mt * 16 + sub * 8 + (lane >> 2);
#pragma unroll
                for (int nt = 0; nt < 8; nt++) {
                    int n = wn * 64 + nt * 8 + (lane & 3) * 2;
                    float h0 = tanh_approx(acc[mt][nt][sub * 2 + 0] + sB1[n]);
                    float h1 = tanh_approx(acc[mt][nt][sub * 2 + 1] + sB1[n + 1]);
                    *(__half2*)(smem + OFF_A + (uint32_t)m * ASTRIDE + n * 2) = __floats2half2_rn(h0, h1);
                }
            }

#pragma unroll
        for (int i = 0; i < 2; i++)
#pragma unroll
            for (int j = 0; j < 8; j++)
#pragma unroll
                for (int c = 0; c < 4; c++) acc[i][j][c] = 0.0f;

        // =================== GEMM2 ============================================
        gemm256<false>(su, W2e, acc, lane, wm, wn, tid, yr, aSts);

        // ---- epilogue: out = c1*(acc + b2) (+ cy*y), scattered ----------------
        bool need_y = (cy != 0.0f);
#pragma unroll
        for (int mt = 0; mt < 2; mt++)
#pragma unroll
            for (int sub = 0; sub < 2; sub++) {
                int m = wm * 32 + mt * 16 + sub * 8 + (lane >> 2);
                if (m < rows) {
                    int row = sPerm[m];
#pragma unroll
                    for (int nt = 0; nt < 8; nt++) {
                        int n = wn * 64 + nt * 8 + (lane & 3) * 2;
                        float2 o;
                        o.x = sC1[n]     * (acc[mt][nt][sub * 2 + 0] + sB2[n]);
                        o.y = sC1[n + 1] * (acc[mt][nt][sub * 2 + 1] + sB2[n + 1]);
                        if (need_y) {
                            float2 yv = *(const float2*)(y + (size_t)row * DF + n);
                            o.x += cy * yv.x;
                            o.y += cy * yv.y;
                        }
                        *(float2*)(out + (size_t)row * DF + n) = o;
                    }
                }
            }
    }

    // ---- self-reset routing state for next graph replay ----------------------
    __syncthreads();
    if (tid == 0) {
        int old = atomicAdd(&g_done, 1);
        if (old == nGrid - 1) {
            for (int q = 0; q < NE; q++) g_cursor[q] = 0;
            g_done = 0;
            __threadfence();
        }
    }
}

// ---------------- launcher ------------------------------------------------------
extern "C" void kernel_launch(void* const* d_in, const int* in_sizes, int n_in,
                              void* d_out, int out_size)
{
    const float* t      = (const float*)d_in[0];
    const float* y      = (const float*)d_in[1];
    const float* W1     = (const float*)d_in[2];
    const float* b1     = (const float*)d_in[3];
    const float* W2     = (const float*)d_in[4];
    const float* b2     = (const float*)d_in[5];
    const float* scales = (const float*)d_in[6];
    const float* sha    = (const float*)d_in[7];
    const float* shb    = (const float*)d_in[8];
    float* out = (float*)d_out;
    int B = in_sizes[0];

    int nb = (B + 255) / 256;
    k_prep<<<512 + nb, 256>>>(W1, W2, t, B);

    cudaFuncSetAttribute(k_moe, cudaFuncAttributeMaxDynamicSharedMemorySize, SMEM_BYTES);
    int grid = (B + TM - 1) / TM + NE;
    k_moe<<<grid, NT, SMEM_BYTES>>>(y, b1, b2, scales, sha, shb, out, grid);
}

// round 9
// speedup vs baseline: 6.3467x; 1.0095x over previous
#include <cuda_runtime.h>
#include <cuda_fp16.h>
#include <stdint.h>
#include <math.h>

#define DF 256
#define NE 8
#define TM 64
#define NT 256
#define MAXB 32768

// ---- smem layout (bytes) ----
#define OFF_PERM 0
#define OFF_B1   512
#define OFF_B2   1536
#define OFF_C1   2560
#define OFF_A    3584
#define ASTRIDE  528                        // 256 halfs + pad (conflict-free LDSM)
#define OFF_BB   (OFF_A + 64*ASTRIDE)       // 37376
#define BSTRIDE  80                         // 32 halfs payload + pad
#define BBUF     20480                      // one fp16 chunk (256n x 32k)
#define SMEM_BYTES (OFF_BB + 3*BBUF)        // 98816 -> 2 CTAs/SM

// ---------------- device scratch (zero-initialized at load) --------------------
__device__ int g_cursor[NE];
__device__ int g_done;
__device__ int g_perm[NE * MAXB];
__device__ __align__(16) __half g_w1[NE * DF * DF];
__device__ __align__(16) __half g_w2[NE * DF * DF];

__device__ __forceinline__ int expert_of(float t) {
    int e = (int)(t * 8.0f);
    if (e > NE - 1) e = NE - 1;
    if (e < 0) e = 0;
    return e;
}

// ---- merged prep: blocks [0,512) convert weights; blocks [512,..) scatter ------
__global__ void k_prep(const float* __restrict__ W1, const float* __restrict__ W2,
                       const float* __restrict__ t, int B) {
    if (blockIdx.x < 512) {
        int v = (blockIdx.x * blockDim.x + threadIdx.x) * 4;
        float4 a = *(const float4*)(W1 + v);
        float4 b = *(const float4*)(W2 + v);
        *(__half2*)(g_w1 + v)     = __floats2half2_rn(a.x, a.y);
        *(__half2*)(g_w1 + v + 2) = __floats2half2_rn(a.z, a.w);
        *(__half2*)(g_w2 + v)     = __floats2half2_rn(b.x, b.y);
        *(__half2*)(g_w2 + v + 2) = __floats2half2_rn(b.z, b.w);
    } else {
        __shared__ int h[NE], bb[NE];
        if (threadIdx.x < NE) h[threadIdx.x] = 0;
        __syncthreads();
        int i = (blockIdx.x - 512) * blockDim.x + threadIdx.x;
        int e = 0, r = 0;
        bool valid = (i < B);
        if (valid) { e = expert_of(t[i]); r = atomicAdd(&h[e], 1); }
        __syncthreads();
        if (threadIdx.x < NE && h[threadIdx.x])
            bb[threadIdx.x] = atomicAdd(&g_cursor[threadIdx.x], h[threadIdx.x]);
        __syncthreads();
        if (valid) g_perm[e * MAXB + bb[e] + r] = i;
    }
}

// ---------------- helpers ----------------------------------------------------------
__device__ __forceinline__ float sigmf(float x) { return 1.0f / (1.0f + expf(-x)); }
__device__ __forceinline__ float tanh_approx(float x) {
    float r;
    asm("tanh.approx.f32 %0, %1;" : "=f"(r) : "f"(x));
    return r;
}

__device__ __forceinline__ void ldsm4(uint32_t* r, uint32_t addr) {
    asm volatile("ldmatrix.sync.aligned.m8n8.x4.shared.b16 {%0,%1,%2,%3}, [%4];"
        : "=r"(r[0]), "=r"(r[1]), "=r"(r[2]), "=r"(r[3]) : "r"(addr));
}
__device__ __forceinline__ void mma_f16(float* d, const uint32_t* a, const uint32_t* b) {
    asm volatile("mma.sync.aligned.m16n8k16.row.col.f32.f16.f16.f32 "
        "{%0,%1,%2,%3}, {%4,%5,%6,%7}, {%8,%9}, {%0,%1,%2,%3};"
        : "+f"(d[0]), "+f"(d[1]), "+f"(d[2]), "+f"(d[3])
        : "r"(a[0]), "r"(a[1]), "r"(a[2]), "r"(a[3]), "r"(b[0]), "r"(b[1]));
}

// cp.async one 32-k weight chunk (256n x 32k fp16) into ring slot `slot`
__device__ __forceinline__ void issue_chunk(uint32_t su, int slot,
                                            const __half* W, int kc, int tid) {
#pragma unroll
    for (int u = 0; u < 4; u++) {
        int v = tid + NT * u;               // 0..1023 16B-lines
        int n = v >> 2, q = v & 3;
        uint32_t dst = su + OFF_BB + slot * BBUF + n * BSTRIDE + q * 16;
        const __half* s = W + (size_t)n * DF + kc * 32 + q * 8;
        asm volatile("cp.async.cg.shared.global [%0], [%1], 16;" :: "r"(dst), "l"(s) : "memory");
    }
    asm volatile("cp.async.commit_group;" ::: "memory");
}

// pack 4 floats -> 4 fp16, 8B STS
__device__ __forceinline__ void sts_f16x4(uint32_t addr, float4 d) {
    __half2 p0 = __floats2half2_rn(d.x, d.y);
    __half2 p1 = __floats2half2_rn(d.z, d.w);
    uint32_t u0 = *reinterpret_cast<uint32_t*>(&p0);
    uint32_t u1 = *reinterpret_cast<uint32_t*>(&p1);
    asm volatile("st.shared.v2.b32 [%0], {%1,%2};" :: "r"(addr), "r"(u0), "r"(u1) : "memory");
}

// GEMM mainloop; 3-slot B ring, ONE barrier per chunk, register-level B-frag
// double-buffering: ldsm of group g+1 issues before MMAs of group g.
// If GATHER: streams A (y rows) chunk kc+2 during MMA of chunk kc.
template<bool GATHER>
__device__ __forceinline__ void gemm256(uint32_t su, const __half* W,
                                        float (&acc)[2][8][4], int lane, int wm, int wn, int tid,
                                        const float* const* yr, uint32_t aSts) {
    uint32_t aBase = su + OFF_A
        + (uint32_t)(wm * 32 + ((lane >> 3) & 1) * 8 + (lane & 7)) * ASTRIDE
        + (uint32_t)(lane >> 4) * 16;
    uint32_t bLane = (uint32_t)(((lane & 7) + (lane >> 4) * 8) * BSTRIDE + ((lane >> 3) & 1) * 16)
                   + (uint32_t)(wn * 64) * BSTRIDE;

    for (int kc = 0; kc < 8; kc++) {
        float4 stg[2];
        if (GATHER && kc < 6) {
#pragma unroll
            for (int u = 0; u < 2; u++) stg[u] = *(const float4*)(yr[u] + (kc + 2) * 32);
        }
        if (kc < 7) { asm volatile("cp.async.wait_group 1;" ::: "memory"); }
        else        { asm volatile("cp.async.wait_group 0;" ::: "memory"); }
        __syncthreads();   // chunk kc readable; slot (kc+2)%3 free for overwrite
        if (kc < 6) issue_chunk(su, (kc + 2) % 3, W, kc + 2, tid);

        uint32_t bBuf = su + OFF_BB + (kc % 3) * BBUF + bLane;
        uint32_t aAddr = aBase + (uint32_t)(kc * 32) * 2;

        // all A frags for this chunk (both k-steps): 16 regs
        uint32_t a[16];
        ldsm4(a + 0,  aAddr);                       // ks0, m 0-15
        ldsm4(a + 4,  aAddr + 16 * ASTRIDE);        // ks0, m 16-31
        ldsm4(a + 8,  aAddr + 32);                  // ks1, m 0-15
        ldsm4(a + 12, aAddr + 16 * ASTRIDE + 32);   // ks1, m 16-31

        // B-frag register pipeline: 8 groups of (2 n-tiles x k16)
        uint32_t bc[4], bn[4];
        ldsm4(bc, bBuf);                            // g=0: ks0, nt 0-1
#pragma unroll
        for (int g = 0; g < 8; g++) {
            if (g < 7) {
                int g2 = g + 1;
                ldsm4(bn, bBuf + (uint32_t)(g2 >> 2) * 32 + (uint32_t)((g2 & 3) * 16) * BSTRIDE);
            }
            const uint32_t* af = a + (g >> 2) * 8;
            int nt = (g & 3) * 2;
            mma_f16(acc[0][nt],     af,     bc + 0);
            mma_f16(acc[1][nt],     af + 4, bc + 0);
            mma_f16(acc[0][nt + 1], af,     bc + 2);
            mma_f16(acc[1][nt + 1], af + 4, bc + 2);
            bc[0] = bn[0]; bc[1] = bn[1]; bc[2] = bn[2]; bc[3] = bn[3];
        }

        if (GATHER && kc < 6) {
#pragma unroll
            for (int u = 0; u < 2; u++)
                sts_f16x4(aSts + (uint32_t)u * 32 * ASTRIDE + (uint32_t)(kc + 2) * 64, stg[u]);
        }
    }
}

// ---------------- main fused MoE kernel --------------------------------------------
__global__ __launch_bounds__(NT, 2) void k_moe(
    const float* __restrict__ y,
    const float* __restrict__ b1, const float* __restrict__ b2,
    const float* __restrict__ scales,
    const float* __restrict__ shifta, const float* __restrict__ shiftb,
    float* __restrict__ out, int nGrid)
{
    extern __shared__ char smem[];
    const int tid  = threadIdx.x;
    const int lane = tid & 31;
    const int wid  = tid >> 5;
    const int wm   = wid & 1;     // 2 warps along M (32 rows each)
    const int wn   = wid >> 1;    // 4 warps along N (64 cols each)

    // ---- block -> (expert, tile) --------------------------------------------
    int bid = blockIdx.x, e = 0, local = -1, acc_t = 0, cnt_e = 0;
#pragma unroll
    for (int q = 0; q < NE; q++) {
        int c  = g_cursor[q];
        int nt = (c + TM - 1) / TM;
        if (local < 0 && bid < acc_t + nt) { e = q; local = bid - acc_t; cnt_e = c; }
        acc_t += nt;
    }

    if (local >= 0) {
        int base = local * TM;
        int rows = cnt_e - base;
        if (rows > TM) rows = TM;

        uint32_t su;
        asm("{ .reg .u64 t; cvta.to.shared.u64 t, %1; cvt.u32.u64 %0, t; }" : "=r"(su) : "l"(smem));

        int*   sPerm = (int*)(smem + OFF_PERM);
        float* sB1   = (float*)(smem + OFF_B1);
        float* sB2   = (float*)(smem + OFF_B2);
        float* sC1   = (float*)(smem + OFF_C1);

        if (tid < TM) sPerm[tid] = (tid < rows) ? g_perm[e * MAXB + base + tid] : g_perm[e * MAXB + base];
        float sa = sigmf(shifta[0]);
        float sb = sigmf(shiftb[0]);
        float cy = 0.5f * (sb - sa);
        sB1[tid] = b1[e * DF + tid];
        sB2[tid] = b2[e * DF + tid];
        sC1[tid] = 0.5f * (sb + sa) * sigmf(scales[tid]);
        __syncthreads();

        const __half* W1e = g_w1 + (size_t)e * DF * DF;
        const __half* W2e = g_w2 + (size_t)e * DF * DF;

        // prologue W1 chunks -> slots 0,1
        issue_chunk(su, 0, W1e, 0, tid);
        issue_chunk(su, 1, W1e, 1, tid);

        // per-thread gather slice: rows (tid>>3) and (tid>>3)+32, f4-slot tid&7
        const float* yr[2];
        {
            int rb = tid >> 3, q = tid & 7;
            yr[0] = y + (size_t)sPerm[rb] * DF + q * 4;
            yr[1] = y + (size_t)sPerm[rb + 32] * DF + q * 4;
        }
        uint32_t aSts = su + OFF_A + (uint32_t)(tid >> 3) * ASTRIDE + (uint32_t)(tid & 7) * 8;

        // gather A chunks 0,1 (prologue)
#pragma unroll
        for (int c = 0; c < 2; c++)
#pragma unroll
            for (int u = 0; u < 2; u++) {
                float4 d = *(const float4*)(yr[u] + c * 32);
                sts_f16x4(aSts + (uint32_t)u * 32 * ASTRIDE + (uint32_t)c * 64, d);
            }

        float acc[2][8][4];
#pragma unroll
        for (int i = 0; i < 2; i++)
#pragma unroll
            for (int j = 0; j < 8; j++)
#pragma unroll
                for (int c = 0; c < 4; c++) acc[i][j][c] = 0.0f;

        // =================== GEMM1 (gather-pipelined) =========================
        gemm256<true>(su, W1e, acc, lane, wm, wn, tid, yr, aSts);

        __syncthreads();   // ring fully read before GEMM2 prologue overwrites
        issue_chunk(su, 0, W2e, 0, tid);
        issue_chunk(su, 1, W2e, 1, tid);

        // ---- H = tanh(acc + b1) -> overwrite A (own rows only) ---------------
#pragma unroll
        for (int mt = 0; mt < 2; mt++)
#pragma unroll
            for (int sub = 0; sub < 2; sub++) {
                int m = wm * 32 + mt * 16 + sub * 8 + (lane >> 2);
#pragma unroll
                for (int nt = 0; nt < 8; nt++) {
                    int n = wn * 64 + nt * 8 + (lane & 3) * 2;
                    float h0 = tanh_approx(acc[mt][nt][sub * 2 + 0] + sB1[n]);
                    float h1 = tanh_approx(acc[mt][nt][sub * 2 + 1] + sB1[n + 1]);
                    *(__half2*)(smem + OFF_A + (uint32_t)m * ASTRIDE + n * 2) = __floats2half2_rn(h0, h1);
                }
            }

#pragma unroll
        for (int i = 0; i < 2; i++)
#pragma unroll
            for (int j = 0; j < 8; j++)
#pragma unroll
                for (int c = 0; c < 4; c++) acc[i][j][c] = 0.0f;

        // =================== GEMM2 ============================================
        gemm256<false>(su, W2e, acc, lane, wm, wn, tid, yr, aSts);

        // ---- epilogue: out = c1*(acc + b2) (+ cy*y), scattered ----------------
        bool need_y = (cy != 0.0f);
#pragma unroll
        for (int mt = 0; mt < 2; mt++)
#pragma unroll
            for (int sub = 0; sub < 2; sub++) {
                int m = wm * 32 + mt * 16 + sub * 8 + (lane >> 2);
                if (m < rows) {
                    int row = sPerm[m];
#pragma unroll
                    for (int nt = 0; nt < 8; nt++) {
                        int n = wn * 64 + nt * 8 + (lane & 3) * 2;
                        float2 o;
                        o.x = sC1[n]     * (acc[mt][nt][sub * 2 + 0] + sB2[n]);
                        o.y = sC1[n + 1] * (acc[mt][nt][sub * 2 + 1] + sB2[n + 1]);
                        if (need_y) {
                            float2 yv = *(const float2*)(y + (size_t)row * DF + n);
                            o.x += cy * yv.x;
                            o.y += cy * yv.y;
                        }
                        *(float2*)(out + (size_t)row * DF + n) = o;
                    }
                }
            }
    }

    // ---- self-reset routing state for next graph replay ----------------------
    __syncthreads();
    if (tid == 0) {
        int old = atomicAdd(&g_done, 1);
        if (old == nGrid - 1) {
            for (int q = 0; q < NE; q++) g_cursor[q] = 0;
            g_done = 0;
            __threadfence();
        }
    }
}

// ---------------- launcher ------------------------------------------------------
extern "C" void kernel_launch(void* const* d_in, const int* in_sizes, int n_in,
                              void* d_out, int out_size)
{
    const float* t      = (const float*)d_in[0];
    const float* y      = (const float*)d_in[1];
    const float* W1     = (const float*)d_in[2];
    const float* b1     = (const float*)d_in[3];
    const float* W2     = (const float*)d_in[4];
    const float* b2     = (const float*)d_in[5];
    const float* scales = (const float*)d_in[6];
    const float* sha    = (const float*)d_in[7];
    const float* shb    = (const float*)d_in[8];
    float* out = (float*)d_out;
    int B = in_sizes[0];

    int nb = (B + 255) / 256;
    k_prep<<<512 + nb, 256>>>(W1, W2, t, B);

    cudaFuncSetAttribute(k_moe, cudaFuncAttributeMaxDynamicSharedMemorySize, SMEM_BYTES);
    int grid = (B + TM - 1) / TM + NE;
    k_moe<<<grid, NT, SMEM_BYTES>>>(y, b1, b2, scales, sha, shb, out, grid);
}

// round 11
// speedup vs baseline: 7.2184x; 1.1373x over previous
#include <cuda_runtime.h>
#include <cuda_fp16.h>
#include <stdint.h>
#include <math.h>

#define DF 256
#define NE 8
#define TM 64
#define NT 256
#define MAXB 32768

// ---- smem layout (bytes) ----
#define OFF_PERM 0
#define OFF_B1   512
#define OFF_B2   1536
#define OFF_C1   2560
#define OFF_A    3584
#define ASTRIDE  528                        // 256 halfs + pad (conflict-free LDSM)
#define SMEM_BYTES (OFF_A + 64*ASTRIDE)     // 37376

// ---------------- device scratch (zero-initialized at load) --------------------
// g_cursor starts zero (static init); reset ONLY by k_moe's tail after each run.
// (R10 bug: zeroing it inside k_prep raced with the same grid's scatter atomics.)
__device__ int g_cursor[NE];
__device__ int g_done;
__device__ int g_perm[NE * MAXB];
// weights in mma-B fragment layout: [mat][e][kc][wn][j][lane] -> uint4
// linear idx = e*8192 + kc*1024 + wn*256 + j*32 + lane
__device__ __align__(16) uint4 g_wf[2][NE * 8 * 4 * 8 * 32];

__device__ __forceinline__ int expert_of(float t) {
    int e = (int)(t * 8.0f);
    if (e > NE - 1) e = NE - 1;
    if (e < 0) e = 0;
    return e;
}

// ---- merged prep: blocks [0,512) build fragment weights; rest scatter ----------
__global__ void k_prep(const float* __restrict__ W1, const float* __restrict__ W2,
                       const float* __restrict__ t, int B) {
    if (blockIdx.x < 512) {
        int i = blockIdx.x * 256 + threadIdx.x;   // 0..131071
        int mat = i >> 16;
        int u   = i & 65535;
        int tt = u & 31, j = (u >> 5) & 7, wn = (u >> 8) & 3;
        int kc = (u >> 10) & 7, e = u >> 13;
        int n  = wn * 64 + j * 8 + (tt >> 2);
        int k0 = kc * 32 + (tt & 3) * 2;
        const float* W = (mat ? W2 : W1) + (size_t)e * DF * DF + (size_t)n * DF + k0;
        uint4 o;
        __half2 h;
        h = __floats2half2_rn(W[0],  W[1]);  o.x = *(uint32_t*)&h;   // ks0 reg0
        h = __floats2half2_rn(W[8],  W[9]);  o.y = *(uint32_t*)&h;   // ks0 reg1
        h = __floats2half2_rn(W[16], W[17]); o.z = *(uint32_t*)&h;   // ks1 reg0
        h = __floats2half2_rn(W[24], W[25]); o.w = *(uint32_t*)&h;   // ks1 reg1
        g_wf[mat][u] = o;
    } else {
        __shared__ int h[NE], bb[NE];
        if (threadIdx.x < NE) h[threadIdx.x] = 0;
        __syncthreads();
        int i = (blockIdx.x - 512) * blockDim.x + threadIdx.x;
        int e = 0, r = 0;
        bool valid = (i < B);
        if (valid) { e = expert_of(t[i]); r = atomicAdd(&h[e], 1); }
        __syncthreads();
        if (threadIdx.x < NE && h[threadIdx.x])
            bb[threadIdx.x] = atomicAdd(&g_cursor[threadIdx.x], h[threadIdx.x]);
        __syncthreads();
        if (valid) g_perm[e * MAXB + bb[e] + r] = i;
    }
}

// ---------------- helpers ----------------------------------------------------------
__device__ __forceinline__ float sigmf(float x) { return 1.0f / (1.0f + expf(-x)); }
__device__ __forceinline__ float tanh_approx(float x) {
    float r;
    asm("tanh.approx.f32 %0, %1;" : "=f"(r) : "f"(x));
    return r;
}

__device__ __forceinline__ void ldsm4(uint32_t* r, uint32_t addr) {
    asm volatile("ldmatrix.sync.aligned.m8n8.x4.shared.b16 {%0,%1,%2,%3}, [%4];"
        : "=r"(r[0]), "=r"(r[1]), "=r"(r[2]), "=r"(r[3]) : "r"(addr));
}
__device__ __forceinline__ void mma_f16(float* d, const uint32_t* a, uint32_t b0, uint32_t b1) {
    asm volatile("mma.sync.aligned.m16n8k16.row.col.f32.f16.f16.f32 "
        "{%0,%1,%2,%3}, {%4,%5,%6,%7}, {%8,%9}, {%0,%1,%2,%3};"
        : "+f"(d[0]), "+f"(d[1]), "+f"(d[2]), "+f"(d[3])
        : "r"(a[0]), "r"(a[1]), "r"(a[2]), "r"(a[3]), "r"(b0), "r"(b1));
}

// pack 4 floats -> 4 fp16, 8B STS
__device__ __forceinline__ void sts_f16x4(uint32_t addr, float4 d) {
    __half2 p0 = __floats2half2_rn(d.x, d.y);
    __half2 p1 = __floats2half2_rn(d.z, d.w);
    uint32_t u0 = *reinterpret_cast<uint32_t*>(&p0);
    uint32_t u1 = *reinterpret_cast<uint32_t*>(&p1);
    asm volatile("st.shared.v2.b32 [%0], {%1,%2};" :: "r"(addr), "r"(u0), "r"(u1) : "memory");
}

// GEMM: A from smem (64 rows, warp reads its wm-half), B frags via LDG.128
// from fragment-ordered global. Barrier-free. Wf points at [e][kc=0][wn][j=0][lane].
__device__ __forceinline__ void gemm256(uint32_t su, const uint4* __restrict__ Wf,
                                        float (&acc)[2][8][4], int lane, int wm) {
    uint32_t aBase = su + OFF_A
        + (uint32_t)(wm * 32 + ((lane >> 3) & 1) * 8 + (lane & 7)) * ASTRIDE
        + (uint32_t)(lane >> 4) * 16;

    uint4 Bv[8];
#pragma unroll
    for (int j = 0; j < 8; j++) Bv[j] = Wf[j * 32];   // chunk 0

#pragma unroll
    for (int kc = 0; kc < 8; kc++) {
        uint32_t aAddr = aBase + (uint32_t)kc * 64;   // 32 halfs per chunk
        uint32_t a[16];
        ldsm4(a + 0,  aAddr);                         // ks0, m 0-15
        ldsm4(a + 4,  aAddr + 16 * ASTRIDE);          // ks0, m 16-31
        ldsm4(a + 8,  aAddr + 32);                    // ks1, m 0-15
        ldsm4(a + 12, aAddr + 16 * ASTRIDE + 32);     // ks1, m 16-31
#pragma unroll
        for (int j = 0; j < 8; j++) {
            uint4 b = Bv[j];
            if (kc < 7) Bv[j] = Wf[(kc + 1) * 1024 + j * 32];   // prefetch next chunk
            mma_f16(acc[0][j], a + 0,  b.x, b.y);
            mma_f16(acc[1][j], a + 4,  b.x, b.y);
            mma_f16(acc[0][j], a + 8,  b.z, b.w);
            mma_f16(acc[1][j], a + 12, b.z, b.w);
        }
    }
}

// ---------------- main fused MoE kernel --------------------------------------------
__global__ __launch_bounds__(NT, 2) void k_moe(
    const float* __restrict__ y,
    const float* __restrict__ b1, const float* __restrict__ b2,
    const float* __restrict__ scales,
    const float* __restrict__ shifta, const float* __restrict__ shiftb,
    float* __restrict__ out, int nGrid)
{
    extern __shared__ char smem[];
    const int tid  = threadIdx.x;
    const int lane = tid & 31;
    const int wid  = tid >> 5;
    const int wm   = wid & 1;     // 2 warps along M (32 rows each)
    const int wn   = wid >> 1;    // 4 warps along N (64 cols each)

    // ---- block -> (expert, tile) --------------------------------------------
    int bid = blockIdx.x, e = 0, local = -1, acc_t = 0, cnt_e = 0;
#pragma unroll
    for (int q = 0; q < NE; q++) {
        int c  = g_cursor[q];
        int nt = (c + TM - 1) / TM;
        if (local < 0 && bid < acc_t + nt) { e = q; local = bid - acc_t; cnt_e = c; }
        acc_t += nt;
    }

    if (local >= 0) {
        int base = local * TM;
        int rows = cnt_e - base;
        if (rows > TM) rows = TM;

        uint32_t su;
        asm("{ .reg .u64 t; cvta.to.shared.u64 t, %1; cvt.u32.u64 %0, t; }" : "=r"(su) : "l"(smem));

        int*   sPerm = (int*)(smem + OFF_PERM);
        float* sB1   = (float*)(smem + OFF_B1);
        float* sB2   = (float*)(smem + OFF_B2);
        float* sC1   = (float*)(smem + OFF_C1);

        if (tid < TM) sPerm[tid] = (tid < rows) ? g_perm[e * MAXB + base + tid] : g_perm[e * MAXB + base];
        float sa = sigmf(shifta[0]);
        float sb = sigmf(shiftb[0]);
        float cy = 0.5f * (sb - sa);
        sB1[tid] = b1[e * DF + tid];
        sB2[tid] = b2[e * DF + tid];
        sC1[tid] = 0.5f * (sb + sa) * sigmf(scales[tid]);
        __syncthreads();

        // ---- gather all of A (y rows -> fp16 smem) ----------------------------
        {
            int rb = tid >> 3, q = tid & 7;
            const float* y0 = y + (size_t)sPerm[rb] * DF + q * 4;
            const float* y1 = y + (size_t)sPerm[rb + 32] * DF + q * 4;
            uint32_t d0 = su + OFF_A + (uint32_t)rb * ASTRIDE + (uint32_t)q * 8;
            uint32_t d1 = d0 + 32 * ASTRIDE;
#pragma unroll
            for (int c = 0; c < 8; c++) {
                float4 v0 = *(const float4*)(y0 + c * 32);
                float4 v1 = *(const float4*)(y1 + c * 32);
                sts_f16x4(d0 + c * 64, v0);
                sts_f16x4(d1 + c * 64, v1);
            }
        }
        __syncthreads();

        const uint4* Wf1 = g_wf[0] + e * 8192 + wn * 256 + lane;
        const uint4* Wf2 = g_wf[1] + e * 8192 + wn * 256 + lane;

        float acc[2][8][4];
#pragma unroll
        for (int i = 0; i < 2; i++)
#pragma unroll
            for (int j = 0; j < 8; j++)
#pragma unroll
                for (int c = 0; c < 4; c++) acc[i][j][c] = 0.0f;

        // =================== GEMM1 (barrier-free) ==============================
        gemm256(su, Wf1, acc, lane, wm);

        __syncthreads();   // all warps done reading A

        // ---- H = tanh(acc + b1) -> overwrite A (own rows only) ---------------
#pragma unroll
        for (int mt = 0; mt < 2; mt++)
#pragma unroll
            for (int sub = 0; sub < 2; sub++) {
                int m = wm * 32 + mt * 16 + sub * 8 + (lane >> 2);
#pragma unroll
                for (int j = 0; j < 8; j++) {
                    int n = wn * 64 + j * 8 + (lane & 3) * 2;
                    float h0 = tanh_approx(acc[mt][j][sub * 2 + 0] + sB1[n]);
                    float h1 = tanh_approx(acc[mt][j][sub * 2 + 1] + sB1[n + 1]);
                    *(__half2*)(smem + OFF_A + (uint32_t)m * ASTRIDE + n * 2) = __floats2half2_rn(h0, h1);
                }
            }
        __syncthreads();   // H fully written

#pragma unroll
        for (int i = 0; i < 2; i++)
#pragma unroll
            for (int j = 0; j < 8; j++)
#pragma unroll
                for (int c = 0; c < 4; c++) acc[i][j][c] = 0.0f;

        // =================== GEMM2 (barrier-free) ==============================
        gemm256(su, Wf2, acc, lane, wm);

        // ---- epilogue: out = c1*(acc + b2) (+ cy*y), scattered ----------------
        bool need_y = (cy != 0.0f);
#pragma unroll
        for (int mt = 0; mt < 2; mt++)
#pragma unroll
            for (int sub = 0; sub < 2; sub++) {
                int m = wm * 32 + mt * 16 + sub * 8 + (lane >> 2);
                if (m < rows) {
                    int row = sPerm[m];
#pragma unroll
                    for (int j = 0; j < 8; j++) {
                        int n = wn * 64 + j * 8 + (lane & 3) * 2;
                        float2 o;
                        o.x = sC1[n]     * (acc[mt][j][sub * 2 + 0] + sB2[n]);
                        o.y = sC1[n + 1] * (acc[mt][j][sub * 2 + 1] + sB2[n + 1]);
                        if (need_y) {
                            float2 yv = *(const float2*)(y + (size_t)row * DF + n);
                            o.x += cy * yv.x;
                            o.y += cy * yv.y;
                        }
                        *(float2*)(out + (size_t)row * DF + n) = o;
                    }
                }
            }
    }

    // ---- self-reset routing state for next graph replay ----------------------
    __syncthreads();
    if (tid == 0) {
        int old = atomicAdd(&g_done, 1);
        if (old == nGrid - 1) {
            for (int q = 0; q < NE; q++) g_cursor[q] = 0;
            g_done = 0;
            __threadfence();
        }
    }
}

// ---------------- launcher ------------------------------------------------------
extern "C" void kernel_launch(void* const* d_in, const int* in_sizes, int n_in,
                              void* d_out, int out_size)
{
    const float* t      = (const float*)d_in[0];
    const float* y      = (const float*)d_in[1];
    const float* W1     = (const float*)d_in[2];
    const float* b1     = (const float*)d_in[3];
    const float* W2     = (const float*)d_in[4];
    const float* b2     = (const float*)d_in[5];
    const float* scales = (const float*)d_in[6];
    const float* sha    = (const float*)d_in[7];
    const float* shb    = (const float*)d_in[8];
    float* out = (float*)d_out;
    int B = in_sizes[0];

    int nb = (B + 255) / 256;
    k_prep<<<512 + nb, 256>>>(W1, W2, t, B);

    cudaFuncSetAttribute(k_moe, cudaFuncAttributeMaxDynamicSharedMemorySize, SMEM_BYTES);
    int grid = (B + TM - 1) / TM + NE;
    k_moe<<<grid, NT, SMEM_BYTES>>>(y, b1, b2, scales, sha, shb, out, grid);
}